// round 2
// baseline (speedup 1.0000x reference)
#include <cuda_runtime.h>
#include <math.h>

#define BB   1024      // batch
#define HH   512       // hidden
#define GG   1536      // 3*H
#define TENC 168
#define TDEC 24

// Persistent device state (allocation-free scratch).
__device__ float g_h[2][BB * HH];        // ping-pong hidden state (4 MB)
__device__ float g_gibase[BB * GG];      // h_t @ W_ih_dec[:, :512]^T + b_ih_dec (6 MB)

__device__ __forceinline__ float sigmoidf_(float x) {
    return 1.0f / (1.0f + expf(-x));
}

// ---------------------------------------------------------------------------
// Fused step kernel.
// MODE: 0 = encoder step, 1 = decoder step, 2 = decoder-input base GEMM
// E:    per-step extra input width (8 enc, 16 dec, unused for BASE)
// WST:  row stride of W (the K=512 GEMM operand)
// WIST: row stride of Wi (the small input weight)
//
// Computes gh = h_in @ W^T over a 64(batch) x 192(gate-col) tile with K=512,
// then fuses biases + gi + GRU nonlinearities and writes h_out (or, for BASE,
// writes raw gemm + b_ih to g_gibase).
// ---------------------------------------------------------------------------
template <int MODE, int E, int WST, int WIST>
__global__ __launch_bounds__(256) void step_kernel(
    int par_in, int par_out,
    const float* __restrict__ W,      // [1536, WST]
    const float* __restrict__ Wi,     // ENC: W_ih_enc [1536,8]; DEC: W_ih_dec [1536,528]
    const float* __restrict__ x,      // ENC: lag_t [1024,8]; DEC: curr_t [1024,16]
    const float* __restrict__ b_ih,   // [1536] (ENC/BASE)
    const float* __restrict__ b_hh)   // [1536] (ENC/DEC)
{
    __shared__ float As[16][68];      // h tile, [k][m], padded
    __shared__ float Ws[16][196];     // W tile, [k][n], n = gate*64 + col, padded
    __shared__ float xs[64 * 16];     // x tile   [m][e], stride E
    __shared__ float Wis[192 * 16];   // Wi tile  [n][e], stride E
    __shared__ float bihs[192];
    __shared__ float bhhs[192];

    const float* __restrict__ h_in = g_h[par_in];

    const int tid = threadIdx.x;
    const int tx = tid & 15;          // 0..15, cols
    const int ty = tid >> 4;          // 0..15, rows
    const int m0 = blockIdx.x * 64;   // batch tile base
    const int j0 = blockIdx.y * 64;   // hidden-col tile base

    // ---- preload per-tile constants ----
    if (tid < 192) {
        const int G = (tid >> 6) * HH + j0 + (tid & 63);
        if (MODE != 1) bihs[tid] = b_ih[G];   // ENC, BASE
        if (MODE != 2) bhhs[tid] = b_hh[G];   // ENC, DEC
    }
    if (MODE != 2) {
        for (int idx = tid; idx < 64 * E; idx += 256)
            xs[idx] = x[m0 * E + idx];
        for (int idx = tid; idx < 192 * E; idx += 256) {
            const int n = idx / E, e = idx - n * E;
            const int G = (n >> 6) * HH + j0 + (n & 63);
            Wis[idx] = Wi[G * WIST + (MODE == 1 ? HH : 0) + e];
        }
    }

    float acc[4][12];
#pragma unroll
    for (int i = 0; i < 4; i++)
#pragma unroll
        for (int j = 0; j < 12; j++) acc[i][j] = 0.0f;

    const int r  = tid >> 2;          // 0..63
    const int kq = (tid & 3) << 2;    // 0,4,8,12

    // ---- K loop: 32 chunks of 16 ----
    for (int k0 = 0; k0 < HH; k0 += 16) {
        // prefetch to registers
        const float4 av  = *(const float4*)(h_in + (size_t)(m0 + r) * HH + k0 + kq);
        const float4 wv0 = *(const float4*)(W + (size_t)(0 * HH + j0 + r) * WST + k0 + kq);
        const float4 wv1 = *(const float4*)(W + (size_t)(1 * HH + j0 + r) * WST + k0 + kq);
        const float4 wv2 = *(const float4*)(W + (size_t)(2 * HH + j0 + r) * WST + k0 + kq);

        __syncthreads();  // previous chunk's compute done
        As[kq + 0][r] = av.x; As[kq + 1][r] = av.y;
        As[kq + 2][r] = av.z; As[kq + 3][r] = av.w;
        Ws[kq + 0][r]       = wv0.x; Ws[kq + 1][r]       = wv0.y;
        Ws[kq + 2][r]       = wv0.z; Ws[kq + 3][r]       = wv0.w;
        Ws[kq + 0][64 + r]  = wv1.x; Ws[kq + 1][64 + r]  = wv1.y;
        Ws[kq + 2][64 + r]  = wv1.z; Ws[kq + 3][64 + r]  = wv1.w;
        Ws[kq + 0][128 + r] = wv2.x; Ws[kq + 1][128 + r] = wv2.y;
        Ws[kq + 2][128 + r] = wv2.z; Ws[kq + 3][128 + r] = wv2.w;
        __syncthreads();

#pragma unroll
        for (int kk = 0; kk < 16; kk++) {
            const float4 a  = *(const float4*)&As[kk][ty << 2];
            const float4 b0 = *(const float4*)&Ws[kk][(tx << 2)];
            const float4 b1 = *(const float4*)&Ws[kk][64 + (tx << 2)];
            const float4 b2 = *(const float4*)&Ws[kk][128 + (tx << 2)];
            const float am[4]  = {a.x, a.y, a.z, a.w};
            const float bn[12] = {b0.x, b0.y, b0.z, b0.w,
                                  b1.x, b1.y, b1.z, b1.w,
                                  b2.x, b2.y, b2.z, b2.w};
#pragma unroll
            for (int i = 0; i < 4; i++)
#pragma unroll
                for (int j = 0; j < 12; j++)
                    acc[i][j] += am[i] * bn[j];
        }
    }

    // ---- epilogue ----
    const int c = tx << 2;            // local col base (0..60)
    if (MODE == 2) {
#pragma unroll
        for (int i = 0; i < 4; i++) {
            const int row = m0 + (ty << 2) + i;
#pragma unroll
            for (int g = 0; g < 3; g++) {
                float4 o;
                o.x = acc[i][g * 4 + 0] + bihs[g * 64 + c + 0];
                o.y = acc[i][g * 4 + 1] + bihs[g * 64 + c + 1];
                o.z = acc[i][g * 4 + 2] + bihs[g * 64 + c + 2];
                o.w = acc[i][g * 4 + 3] + bihs[g * 64 + c + 3];
                *(float4*)&g_gibase[(size_t)row * GG + g * HH + j0 + c] = o;
            }
        }
    } else {
        float* __restrict__ h_out = g_h[par_out];
#pragma unroll
        for (int i = 0; i < 4; i++) {
            const int m = (ty << 2) + i;      // local batch row
            const int row = m0 + m;           // global batch row

            float gi[3][4];
            if (MODE == 0) {
#pragma unroll
                for (int g = 0; g < 3; g++)
#pragma unroll
                    for (int jj = 0; jj < 4; jj++) {
                        float s = bihs[g * 64 + c + jj];
#pragma unroll
                        for (int e = 0; e < E; e++)
                            s += xs[m * E + e] * Wis[(g * 64 + c + jj) * E + e];
                        gi[g][jj] = s;
                    }
            } else {
#pragma unroll
                for (int g = 0; g < 3; g++) {
                    const float4 gb = *(const float4*)&g_gibase[(size_t)row * GG + g * HH + j0 + c];
                    gi[g][0] = gb.x; gi[g][1] = gb.y; gi[g][2] = gb.z; gi[g][3] = gb.w;
#pragma unroll
                    for (int jj = 0; jj < 4; jj++) {
                        float s = gi[g][jj];
#pragma unroll
                        for (int e = 0; e < E; e++)
                            s += xs[m * E + e] * Wis[(g * 64 + c + jj) * E + e];
                        gi[g][jj] = s;
                    }
                }
            }

            const float4 hp = *(const float4*)(h_in + (size_t)row * HH + j0 + c);
            const float hpv[4] = {hp.x, hp.y, hp.z, hp.w};
            float ov[4];
#pragma unroll
            for (int jj = 0; jj < 4; jj++) {
                const float rr = sigmoidf_(gi[0][jj] + acc[i][jj]     + bhhs[c + jj]);
                const float zz = sigmoidf_(gi[1][jj] + acc[i][4 + jj] + bhhs[64 + c + jj]);
                const float nn = tanhf(gi[2][jj] + rr * (acc[i][8 + jj] + bhhs[128 + c + jj]));
                ov[jj] = (1.0f - zz) * nn + zz * hpv[jj];
            }
            float4 o; o.x = ov[0]; o.y = ov[1]; o.z = ov[2]; o.w = ov[3];
            *(float4*)(h_out + (size_t)row * HH + j0 + c) = o;
        }
    }
}

// Zero one hidden-state buffer.
__global__ void zero_h_kernel(int buf) {
    for (int i = blockIdx.x * blockDim.x + threadIdx.x; i < BB * HH;
         i += gridDim.x * blockDim.x)
        g_h[buf][i] = 0.0f;
}

// pred[b, t] = h[b,:] . W_dense + b_dense   (one warp per batch row)
__global__ void pred_kernel(int par, const float* __restrict__ Wd,
                            const float* __restrict__ bd,
                            float* __restrict__ out, int t) {
    const int warp = blockIdx.x * (blockDim.x >> 5) + (threadIdx.x >> 5);
    const int lane = threadIdx.x & 31;
    const float* __restrict__ h = g_h[par] + (size_t)warp * HH;
    float s = 0.0f;
#pragma unroll
    for (int k = lane; k < HH; k += 32) s += h[k] * Wd[k];
#pragma unroll
    for (int off = 16; off; off >>= 1)
        s += __shfl_down_sync(0xffffffffu, s, off);
    if (lane == 0) out[warp * TDEC + t] = s + bd[0];
}

extern "C" void kernel_launch(void* const* d_in, const int* in_sizes, int n_in,
                              void* d_out, int out_size) {
    const float* lag      = (const float*)d_in[0];   // [168,1024,8]
    const float* curr     = (const float*)d_in[1];   // [24,1024,16]
    const float* W_ih_enc = (const float*)d_in[2];   // [1536,8]
    const float* W_hh_enc = (const float*)d_in[3];   // [1536,512]
    const float* b_ih_enc = (const float*)d_in[4];   // [1536]
    const float* b_hh_enc = (const float*)d_in[5];   // [1536]
    const float* W_ih_dec = (const float*)d_in[6];   // [1536,528]
    const float* W_hh_dec = (const float*)d_in[7];   // [1536,512]
    const float* b_ih_dec = (const float*)d_in[8];   // [1536]
    const float* b_hh_dec = (const float*)d_in[9];   // [1536]
    const float* W_dense  = (const float*)d_in[10];  // [1,512]
    const float* b_dense  = (const float*)d_in[11];  // [1]
    float* out = (float*)d_out;                      // [1024,24]

    const dim3 grid(16, 8);  // 16 batch tiles x 8 col tiles

    // ---- encoder ----
    zero_h_kernel<<<256, 256>>>(0);
    int p = 0;
    for (int t = 0; t < TENC; t++) {
        step_kernel<0, 8, 512, 8><<<grid, 256>>>(
            p, p ^ 1, W_hh_enc, W_ih_enc,
            lag + (size_t)t * BB * 8, b_ih_enc, b_hh_enc);
        p ^= 1;
    }
    // 168 is even -> h_t lives in g_h[0]

    // ---- decoder input base: gi_base = h_t @ W_ih_dec[:, :512]^T + b_ih_dec ----
    step_kernel<2, 1, 528, 528><<<grid, 256>>>(
        p, 0, W_ih_dec, (const float*)0, (const float*)0, b_ih_dec, (const float*)0);

    // ---- decoder ----
    zero_h_kernel<<<256, 256>>>(p ^ 1);
    int q = p ^ 1;
    for (int t = 0; t < TDEC; t++) {
        step_kernel<1, 16, 512, 528><<<grid, 256>>>(
            q, q ^ 1, W_hh_dec, W_ih_dec,
            curr + (size_t)t * BB * 16, b_ih_dec, b_hh_dec);
        q ^= 1;
        pred_kernel<<<128, 256>>>(q, W_dense, b_dense, out, t);
    }
}

// round 3
// speedup vs baseline: 1.0053x; 1.0053x over previous
#include <cuda_runtime.h>
#include <math.h>

#define BB   1024      // batch
#define HH   512       // hidden
#define GG   1536      // 3*H
#define TENC 168
#define TDEC 24

// Persistent device state (allocation-free scratch).
__device__ float g_h[2][BB * HH];        // ping-pong hidden state (4 MB)
__device__ float g_gibase[BB * GG];      // h_t @ W_ih_dec[:, :512]^T + b_ih_dec (6 MB)

__device__ __forceinline__ float sigmoidf_(float x) {
    return 1.0f / (1.0f + expf(-x));
}

// ---------------------------------------------------------------------------
// Fused step kernel.
// MODE: 0 = encoder step, 1 = decoder step, 2 = decoder-input base GEMM
// E:    per-step extra input width (8 enc, 16 dec, unused for BASE)
// WST:  row stride of W (the K=512 GEMM operand)
// WIST: row stride of Wi (the small input weight)
//
// Computes gh = h_in @ W^T over a 64(batch) x 192(gate-col) tile with K=512,
// then fuses biases + gi + GRU nonlinearities and writes h_out (or, for BASE,
// writes raw gemm + b_ih to g_gibase).
// ---------------------------------------------------------------------------
template <int MODE, int E, int WST, int WIST>
__global__ __launch_bounds__(256) void step_kernel(
    int par_in, int par_out,
    const float* __restrict__ W,      // [1536, WST]
    const float* __restrict__ Wi,     // ENC: W_ih_enc [1536,8]; DEC: W_ih_dec [1536,528]
    const float* __restrict__ x,      // ENC: lag_t [1024,8]; DEC: curr_t [1024,16]
    const float* __restrict__ b_ih,   // [1536] (ENC/BASE)
    const float* __restrict__ b_hh)   // [1536] (ENC/DEC)
{
    __shared__ float As[16][68];      // h tile, [k][m], padded
    __shared__ float Ws[16][196];     // W tile, [k][n], n = gate*64 + col, padded
    __shared__ float xs[64 * 16];     // x tile   [m][e], stride E
    __shared__ float Wis[192 * 16];   // Wi tile  [n][e], stride E
    __shared__ float bihs[192];
    __shared__ float bhhs[192];

    const float* __restrict__ h_in = g_h[par_in];

    const int tid = threadIdx.x;
    const int tx = tid & 15;          // 0..15, cols
    const int ty = tid >> 4;          // 0..15, rows
    const int m0 = blockIdx.x * 64;   // batch tile base
    const int j0 = blockIdx.y * 64;   // hidden-col tile base

    // ---- preload per-tile constants ----
    if (tid < 192) {
        const int G = (tid >> 6) * HH + j0 + (tid & 63);
        if (MODE != 1) bihs[tid] = b_ih[G];   // ENC, BASE
        if (MODE != 2) bhhs[tid] = b_hh[G];   // ENC, DEC
    }
    if (MODE != 2) {
        for (int idx = tid; idx < 64 * E; idx += 256)
            xs[idx] = x[m0 * E + idx];
        for (int idx = tid; idx < 192 * E; idx += 256) {
            const int n = idx / E, e = idx - n * E;
            const int G = (n >> 6) * HH + j0 + (n & 63);
            Wis[idx] = Wi[G * WIST + (MODE == 1 ? HH : 0) + e];
        }
    }

    float acc[4][12];
#pragma unroll
    for (int i = 0; i < 4; i++)
#pragma unroll
        for (int j = 0; j < 12; j++) acc[i][j] = 0.0f;

    const int r  = tid >> 2;          // 0..63
    const int kq = (tid & 3) << 2;    // 0,4,8,12

    // ---- K loop: 32 chunks of 16 ----
    for (int k0 = 0; k0 < HH; k0 += 16) {
        // prefetch to registers
        const float4 av  = *(const float4*)(h_in + (size_t)(m0 + r) * HH + k0 + kq);
        const float4 wv0 = *(const float4*)(W + (size_t)(0 * HH + j0 + r) * WST + k0 + kq);
        const float4 wv1 = *(const float4*)(W + (size_t)(1 * HH + j0 + r) * WST + k0 + kq);
        const float4 wv2 = *(const float4*)(W + (size_t)(2 * HH + j0 + r) * WST + k0 + kq);

        __syncthreads();  // previous chunk's compute done
        As[kq + 0][r] = av.x; As[kq + 1][r] = av.y;
        As[kq + 2][r] = av.z; As[kq + 3][r] = av.w;
        Ws[kq + 0][r]       = wv0.x; Ws[kq + 1][r]       = wv0.y;
        Ws[kq + 2][r]       = wv0.z; Ws[kq + 3][r]       = wv0.w;
        Ws[kq + 0][64 + r]  = wv1.x; Ws[kq + 1][64 + r]  = wv1.y;
        Ws[kq + 2][64 + r]  = wv1.z; Ws[kq + 3][64 + r]  = wv1.w;
        Ws[kq + 0][128 + r] = wv2.x; Ws[kq + 1][128 + r] = wv2.y;
        Ws[kq + 2][128 + r] = wv2.z; Ws[kq + 3][128 + r] = wv2.w;
        __syncthreads();

#pragma unroll
        for (int kk = 0; kk < 16; kk++) {
            const float4 a  = *(const float4*)&As[kk][ty << 2];
            const float4 b0 = *(const float4*)&Ws[kk][(tx << 2)];
            const float4 b1 = *(const float4*)&Ws[kk][64 + (tx << 2)];
            const float4 b2 = *(const float4*)&Ws[kk][128 + (tx << 2)];
            const float am[4]  = {a.x, a.y, a.z, a.w};
            const float bn[12] = {b0.x, b0.y, b0.z, b0.w,
                                  b1.x, b1.y, b1.z, b1.w,
                                  b2.x, b2.y, b2.z, b2.w};
#pragma unroll
            for (int i = 0; i < 4; i++)
#pragma unroll
                for (int j = 0; j < 12; j++)
                    acc[i][j] += am[i] * bn[j];
        }
    }

    // ---- epilogue ----
    const int c = tx << 2;            // local col base (0..60)
    if (MODE == 2) {
#pragma unroll
        for (int i = 0; i < 4; i++) {
            const int row = m0 + (ty << 2) + i;
#pragma unroll
            for (int g = 0; g < 3; g++) {
                float4 o;
                o.x = acc[i][g * 4 + 0] + bihs[g * 64 + c + 0];
                o.y = acc[i][g * 4 + 1] + bihs[g * 64 + c + 1];
                o.z = acc[i][g * 4 + 2] + bihs[g * 64 + c + 2];
                o.w = acc[i][g * 4 + 3] + bihs[g * 64 + c + 3];
                *(float4*)&g_gibase[(size_t)row * GG + g * HH + j0 + c] = o;
            }
        }
    } else {
        float* __restrict__ h_out = g_h[par_out];
#pragma unroll
        for (int i = 0; i < 4; i++) {
            const int m = (ty << 2) + i;      // local batch row
            const int row = m0 + m;           // global batch row

            float gi[3][4];
            if (MODE == 0) {
#pragma unroll
                for (int g = 0; g < 3; g++)
#pragma unroll
                    for (int jj = 0; jj < 4; jj++) {
                        float s = bihs[g * 64 + c + jj];
#pragma unroll
                        for (int e = 0; e < E; e++)
                            s += xs[m * E + e] * Wis[(g * 64 + c + jj) * E + e];
                        gi[g][jj] = s;
                    }
            } else {
#pragma unroll
                for (int g = 0; g < 3; g++) {
                    const float4 gb = *(const float4*)&g_gibase[(size_t)row * GG + g * HH + j0 + c];
                    gi[g][0] = gb.x; gi[g][1] = gb.y; gi[g][2] = gb.z; gi[g][3] = gb.w;
#pragma unroll
                    for (int jj = 0; jj < 4; jj++) {
                        float s = gi[g][jj];
#pragma unroll
                        for (int e = 0; e < E; e++)
                            s += xs[m * E + e] * Wis[(g * 64 + c + jj) * E + e];
                        gi[g][jj] = s;
                    }
                }
            }

            const float4 hp = *(const float4*)(h_in + (size_t)row * HH + j0 + c);
            const float hpv[4] = {hp.x, hp.y, hp.z, hp.w};
            float ov[4];
#pragma unroll
            for (int jj = 0; jj < 4; jj++) {
                const float rr = sigmoidf_(gi[0][jj] + acc[i][jj]     + bhhs[c + jj]);
                const float zz = sigmoidf_(gi[1][jj] + acc[i][4 + jj] + bhhs[64 + c + jj]);
                const float nn = tanhf(gi[2][jj] + rr * (acc[i][8 + jj] + bhhs[128 + c + jj]));
                ov[jj] = (1.0f - zz) * nn + zz * hpv[jj];
            }
            float4 o; o.x = ov[0]; o.y = ov[1]; o.z = ov[2]; o.w = ov[3];
            *(float4*)(h_out + (size_t)row * HH + j0 + c) = o;
        }
    }
}

// Zero one hidden-state buffer.
__global__ void zero_h_kernel(int buf) {
    for (int i = blockIdx.x * blockDim.x + threadIdx.x; i < BB * HH;
         i += gridDim.x * blockDim.x)
        g_h[buf][i] = 0.0f;
}

// pred[b, t] = h[b,:] . W_dense + b_dense   (one warp per batch row)
__global__ void pred_kernel(int par, const float* __restrict__ Wd,
                            const float* __restrict__ bd,
                            float* __restrict__ out, int t) {
    const int warp = blockIdx.x * (blockDim.x >> 5) + (threadIdx.x >> 5);
    const int lane = threadIdx.x & 31;
    const float* __restrict__ h = g_h[par] + (size_t)warp * HH;
    float s = 0.0f;
#pragma unroll
    for (int k = lane; k < HH; k += 32) s += h[k] * Wd[k];
#pragma unroll
    for (int off = 16; off; off >>= 1)
        s += __shfl_down_sync(0xffffffffu, s, off);
    if (lane == 0) out[warp * TDEC + t] = s + bd[0];
}

extern "C" void kernel_launch(void* const* d_in, const int* in_sizes, int n_in,
                              void* d_out, int out_size) {
    const float* lag      = (const float*)d_in[0];   // [168,1024,8]
    const float* curr     = (const float*)d_in[1];   // [24,1024,16]
    const float* W_ih_enc = (const float*)d_in[2];   // [1536,8]
    const float* W_hh_enc = (const float*)d_in[3];   // [1536,512]
    const float* b_ih_enc = (const float*)d_in[4];   // [1536]
    const float* b_hh_enc = (const float*)d_in[5];   // [1536]
    const float* W_ih_dec = (const float*)d_in[6];   // [1536,528]
    const float* W_hh_dec = (const float*)d_in[7];   // [1536,512]
    const float* b_ih_dec = (const float*)d_in[8];   // [1536]
    const float* b_hh_dec = (const float*)d_in[9];   // [1536]
    const float* W_dense  = (const float*)d_in[10];  // [1,512]
    const float* b_dense  = (const float*)d_in[11];  // [1]
    float* out = (float*)d_out;                      // [1024,24]

    const dim3 grid(16, 8);  // 16 batch tiles x 8 col tiles

    // ---- encoder ----
    zero_h_kernel<<<256, 256>>>(0);
    int p = 0;
    for (int t = 0; t < TENC; t++) {
        step_kernel<0, 8, 512, 8><<<grid, 256>>>(
            p, p ^ 1, W_hh_enc, W_ih_enc,
            lag + (size_t)t * BB * 8, b_ih_enc, b_hh_enc);
        p ^= 1;
    }
    // 168 is even -> h_t lives in g_h[0]

    // ---- decoder input base: gi_base = h_t @ W_ih_dec[:, :512]^T + b_ih_dec ----
    step_kernel<2, 1, 528, 528><<<grid, 256>>>(
        p, 0, W_ih_dec, (const float*)0, (const float*)0, b_ih_dec, (const float*)0);

    // ---- decoder ----
    zero_h_kernel<<<256, 256>>>(p ^ 1);
    int q = p ^ 1;
    for (int t = 0; t < TDEC; t++) {
        step_kernel<1, 16, 512, 528><<<grid, 256>>>(
            q, q ^ 1, W_hh_dec, W_ih_dec,
            curr + (size_t)t * BB * 16, b_ih_dec, b_hh_dec);
        q ^= 1;
        pred_kernel<<<128, 256>>>(q, W_dense, b_dense, out, t);
    }
}

// round 4
// speedup vs baseline: 1.4679x; 1.4601x over previous
#include <cuda_runtime.h>
#include <cuda_bf16.h>
#include <math.h>
#include <stdint.h>

#define BB   1024
#define HH   512
#define GG   1536
#define KE   528      // 512 h + 16 input ext
#define NCH  33       // K chunks of 16
#define TENC 168
#define TDEC 24

// ---------------- persistent device state ----------------
__device__ float g_h[2][BB * HH];
__device__ __align__(16) __nv_bfloat16 g_hhi[2][BB * HH];
__device__ __align__(16) __nv_bfloat16 g_hlo[2][BB * HH];
__device__ float g_gibase[BB * GG];
__device__ __align__(16) __nv_bfloat16 g_B[2][2][GG * KE];   // [enc/dec][hi/lo]
__device__ __align__(16) __nv_bfloat16 g_Bn[2][2][HH * 16];  // gate-n input weights
__device__ __align__(16) __nv_bfloat16 g_xe[2][TENC * BB * 16];
__device__ __align__(16) __nv_bfloat16 g_xd[2][TDEC * BB * 16];
__device__ float g_bc[2][4 * HH];   // combined biases

__device__ __forceinline__ float sigmoidf_(float x) { return 1.0f / (1.0f + expf(-x)); }

__device__ __forceinline__ void ldm4(uint32_t r[4], const __nv_bfloat16* p) {
    uint32_t a = (uint32_t)__cvta_generic_to_shared(p);
    asm volatile("ldmatrix.sync.aligned.m8n8.x4.shared.b16 {%0,%1,%2,%3}, [%4];"
                 : "=r"(r[0]), "=r"(r[1]), "=r"(r[2]), "=r"(r[3]) : "r"(a));
}
__device__ __forceinline__ void mmab(float* d, const uint32_t* a, uint32_t b0, uint32_t b1) {
    asm volatile(
        "mma.sync.aligned.m16n8k16.row.col.f32.bf16.bf16.f32 "
        "{%0,%1,%2,%3},{%4,%5,%6,%7},{%8,%9},{%0,%1,%2,%3};"
        : "+f"(d[0]), "+f"(d[1]), "+f"(d[2]), "+f"(d[3])
        : "r"(a[0]), "r"(a[1]), "r"(a[2]), "r"(a[3]), "r"(b0), "r"(b1));
}
__device__ __forceinline__ void cpa(const __nv_bfloat16* dst, const __nv_bfloat16* src) {
    uint32_t d = (uint32_t)__cvta_generic_to_shared(dst);
    asm volatile("cp.async.cg.shared.global [%0], [%1], 16;" :: "r"(d), "l"(src));
}

// ---------------- prep kernels (once per launch) ----------------
__global__ void prep_B_kernel(const float* __restrict__ Whe, const float* __restrict__ Wie,
                              const float* __restrict__ Whd, const float* __restrict__ Wid) {
    for (int idx = blockIdx.x * blockDim.x + threadIdx.x; idx < 2 * GG * KE;
         idx += gridDim.x * blockDim.x) {
        const int which = idx / (GG * KE), r = idx - which * (GG * KE);
        const int G = r / KE, k = r - G * KE;
        float w;
        if (which == 0)
            w = (k < 512) ? Whe[G * 512 + k]
                          : ((G < 1024 && (k - 512) < 8) ? Wie[G * 8 + (k - 512)] : 0.0f);
        else
            w = (k < 512) ? Whd[G * 512 + k]
                          : ((G < 1024) ? Wid[(size_t)G * 528 + k] : 0.0f);
        const __nv_bfloat16 hi = __float2bfloat16_rn(w);
        g_B[which][0][r] = hi;
        g_B[which][1][r] = __float2bfloat16_rn(w - __bfloat162float(hi));
    }
}
__global__ void prep_Bn_kernel(const float* __restrict__ Wie, const float* __restrict__ Wid) {
    for (int idx = blockIdx.x * blockDim.x + threadIdx.x; idx < 2 * HH * 16;
         idx += gridDim.x * blockDim.x) {
        const int which = idx / (HH * 16), r = idx - which * (HH * 16);
        const int j = r >> 4, e = r & 15;
        float w;
        if (which == 0) w = (e < 8) ? Wie[(1024 + j) * 8 + e] : 0.0f;
        else            w = Wid[(size_t)(1024 + j) * 528 + 512 + e];
        const __nv_bfloat16 hi = __float2bfloat16_rn(w);
        g_Bn[which][0][r] = hi;
        g_Bn[which][1][r] = __float2bfloat16_rn(w - __bfloat162float(hi));
    }
}
__global__ void prep_x_kernel(const float* __restrict__ lag, const float* __restrict__ curr) {
    const int NE = TENC * BB * 16;
    for (int idx = blockIdx.x * blockDim.x + threadIdx.x; idx < NE + TDEC * BB * 16;
         idx += gridDim.x * blockDim.x) {
        if (idx < NE) {
            const int e = idx & 15;
            const float v = (e < 8) ? lag[(idx >> 4) * 8 + e] : 0.0f;
            const __nv_bfloat16 hi = __float2bfloat16_rn(v);
            g_xe[0][idx] = hi;
            g_xe[1][idx] = __float2bfloat16_rn(v - __bfloat162float(hi));
        } else {
            const int r = idx - NE;
            const float v = curr[r];
            const __nv_bfloat16 hi = __float2bfloat16_rn(v);
            g_xd[0][r] = hi;
            g_xd[1][r] = __float2bfloat16_rn(v - __bfloat162float(hi));
        }
    }
}
__global__ void prep_bc_kernel(const float* __restrict__ bie, const float* __restrict__ bhe,
                               const float* __restrict__ bid, const float* __restrict__ bhd) {
    for (int c = blockIdx.x * blockDim.x + threadIdx.x; c < HH;
         c += gridDim.x * blockDim.x) {
        g_bc[0][c]            = bie[c] + bhe[c];
        g_bc[0][HH + c]       = bie[512 + c] + bhe[512 + c];
        g_bc[0][2 * HH + c]   = bie[1024 + c];
        g_bc[0][3 * HH + c]   = bhe[1024 + c];
        g_bc[1][c]            = bhd[c];
        g_bc[1][HH + c]       = bhd[512 + c];
        g_bc[1][2 * HH + c]   = 0.0f;
        g_bc[1][3 * HH + c]   = bhd[1024 + c];
    }
}
__global__ void zero_h_kernel(int buf) {
    for (int i = blockIdx.x * blockDim.x + threadIdx.x; i < BB * HH;
         i += gridDim.x * blockDim.x) {
        g_h[buf][i] = 0.0f;
        g_hhi[buf][i] = __float2bfloat16_rn(0.0f);
        g_hlo[buf][i] = __float2bfloat16_rn(0.0f);
    }
}

// ---------------- main tensor-core step kernel ----------------
// Tile: M=64 (batch) x 64 hidden cols x 3 gates, K=528 in 33 chunks of 16.
template <int DEC>
__global__ __launch_bounds__(256) void mma_step(int pi, int po, int t) {
    __shared__ __align__(16) __nv_bfloat16 As[2][2][2][64][8];   // [buf][split][khalf][row][8]
    __shared__ __align__(16) __nv_bfloat16 Bs[2][2][2][192][8];
    __shared__ __align__(16) __nv_bfloat16 Bn[2][2][64][8];      // [split][khalf][row][8]

    const int tid = threadIdx.x;
    const int w = tid >> 5, l = tid & 31;
    const int m0 = blockIdx.x * 64, j0 = blockIdx.y * 64;

    const __nv_bfloat16* __restrict__ Ahi_g = g_hhi[pi];
    const __nv_bfloat16* __restrict__ Alo_g = g_hlo[pi];
    const __nv_bfloat16* __restrict__ Bhi_g = g_B[DEC][0];
    const __nv_bfloat16* __restrict__ Blo_g = g_B[DEC][1];
    const __nv_bfloat16* __restrict__ xhi = (DEC ? g_xd[0] : g_xe[0]) + t * BB * 16;
    const __nv_bfloat16* __restrict__ xlo = (DEC ? g_xd[1] : g_xe[1]) + t * BB * 16;

    // Bn tile (once; joins chunk-0 commit group)
    {
        const int sp = tid >> 7, rh = tid & 127, row = rh >> 1, hf = rh & 1;
        cpa(&Bn[sp][hf][row][0], &g_Bn[DEC][sp][(j0 + row) * 16 + hf * 8]);
    }

    auto load_chunk = [&](int ch, int buf) {
        const int k0 = ch * 16;
        {   // A: 256 transfers
            const int sp = tid >> 7, rh = tid & 127, row = rh >> 1, hf = rh & 1;
            const __nv_bfloat16* src;
            if (ch < 32) src = (sp ? Alo_g : Ahi_g) + (size_t)(m0 + row) * HH + k0 + hf * 8;
            else         src = (sp ? xlo : xhi) + (m0 + row) * 16 + hf * 8;
            cpa(&As[buf][sp][hf][row][0], src);
        }
#pragma unroll
        for (int j = 0; j < 3; j++) {   // B: 768 transfers
            const int i = j * 256 + tid;
            const int sp = i / 384, rem = i - sp * 384;
            const int row = rem >> 1, hf = rem & 1;
            const int G = (row >> 6) * HH + j0 + (row & 63);
            cpa(&Bs[buf][sp][hf][row][0], (sp ? Blo_g : Bhi_g) + (size_t)G * KE + k0 + hf * 8);
        }
        asm volatile("cp.async.commit_group;");
    };

    float acc[2][3][2][4];    // [mi][gate][nj][quad]
    float accn[2][2][4];
#pragma unroll
    for (int a = 0; a < 2; a++)
#pragma unroll
        for (int g = 0; g < 3; g++)
#pragma unroll
            for (int b = 0; b < 2; b++)
#pragma unroll
                for (int q = 0; q < 4; q++) acc[a][g][b][q] = 0.0f;
#pragma unroll
    for (int a = 0; a < 2; a++)
#pragma unroll
        for (int b = 0; b < 2; b++)
#pragma unroll
            for (int q = 0; q < 4; q++) accn[a][b][q] = 0.0f;

    const int mbase = (w >> 2) * 32;     // warp's m offset in tile
    const int nloc  = (w & 3) * 16;      // warp's col offset within 64
    const int arow  = l & 15;            // ldmatrix A row in m16
    const int ahalf = (l >> 4) & 1;
    const int brow  = (l & 7) + ((l >> 4) & 1) * 8;
    const int bhalf = (l >> 3) & 1;

    load_chunk(0, 0);

    for (int ch = 0; ch < NCH; ch++) {
        const int buf = ch & 1;
        if (ch + 1 < NCH) {
            load_chunk(ch + 1, buf ^ 1);
            asm volatile("cp.async.wait_group 1;");
        } else {
            asm volatile("cp.async.wait_group 0;");
        }
        __syncthreads();

        uint32_t ahi[2][4], alo[2][4];
#pragma unroll
        for (int mi = 0; mi < 2; mi++) {
            ldm4(ahi[mi], &As[buf][0][ahalf][mbase + mi * 16 + arow][0]);
            ldm4(alo[mi], &As[buf][1][ahalf][mbase + mi * 16 + arow][0]);
        }
        uint32_t bhi[3][4], blo[3][4];
#pragma unroll
        for (int g = 0; g < 3; g++) {
            ldm4(bhi[g], &Bs[buf][0][bhalf][g * 64 + nloc + brow][0]);
            ldm4(blo[g], &Bs[buf][1][bhalf][g * 64 + nloc + brow][0]);
        }
#pragma unroll
        for (int mi = 0; mi < 2; mi++)
#pragma unroll
            for (int g = 0; g < 3; g++)
#pragma unroll
                for (int nj = 0; nj < 2; nj++) {
                    mmab(acc[mi][g][nj], ahi[mi], bhi[g][nj * 2], bhi[g][nj * 2 + 1]);
                    mmab(acc[mi][g][nj], ahi[mi], blo[g][nj * 2], blo[g][nj * 2 + 1]);
                    mmab(acc[mi][g][nj], alo[mi], bhi[g][nj * 2], bhi[g][nj * 2 + 1]);
                }
        if (ch == NCH - 1) {   // gate-n input term
            uint32_t nhi[4], nlo[4];
            ldm4(nhi, &Bn[0][bhalf][nloc + brow][0]);
            ldm4(nlo, &Bn[1][bhalf][nloc + brow][0]);
#pragma unroll
            for (int mi = 0; mi < 2; mi++)
#pragma unroll
                for (int nj = 0; nj < 2; nj++) {
                    mmab(accn[mi][nj], ahi[mi], nhi[nj * 2], nhi[nj * 2 + 1]);
                    mmab(accn[mi][nj], ahi[mi], nlo[nj * 2], nlo[nj * 2 + 1]);
                    mmab(accn[mi][nj], alo[mi], nhi[nj * 2], nhi[nj * 2 + 1]);
                }
        }
        __syncthreads();
    }

    // ---- fused GRU epilogue ----
    const int qr = l >> 2;          // row within m16 half
    const int qc = (l & 3) * 2;     // col pair base within n8
    float* __restrict__ h_out = g_h[po];
    __nv_bfloat16* __restrict__ hhi_o = g_hhi[po];
    __nv_bfloat16* __restrict__ hlo_o = g_hlo[po];
    const float* __restrict__ hprev = g_h[pi];
    const float* __restrict__ bc = g_bc[DEC];

#pragma unroll
    for (int mi = 0; mi < 2; mi++)
#pragma unroll
        for (int nj = 0; nj < 2; nj++) {
            const int cb = j0 + nloc + nj * 8 + qc;   // even
#pragma unroll
            for (int hf = 0; hf < 2; hf++) {
                const int m = m0 + mbase + mi * 16 + qr + hf * 8;
                const float2 hp = *(const float2*)&hprev[(size_t)m * HH + cb];
                float2 gr = {0.f, 0.f}, gz = {0.f, 0.f}, gn = {0.f, 0.f};
                if (DEC) {
                    gr = *(const float2*)&g_gibase[(size_t)m * GG + cb];
                    gz = *(const float2*)&g_gibase[(size_t)m * GG + HH + cb];
                    gn = *(const float2*)&g_gibase[(size_t)m * GG + 2 * HH + cb];
                }
                float hv[2];
#pragma unroll
                for (int cc = 0; cc < 2; cc++) {
                    const int q = hf * 2 + cc, c = cb + cc;
                    const float ibr = cc ? gr.y : gr.x;
                    const float ibz = cc ? gz.y : gz.x;
                    const float ibn = cc ? gn.y : gn.x;
                    const float rr = sigmoidf_(acc[mi][0][nj][q] + ibr + bc[c]);
                    const float zz = sigmoidf_(acc[mi][1][nj][q] + ibz + bc[HH + c]);
                    const float in_ = accn[mi][nj][q] + ibn + bc[2 * HH + c];
                    const float ghn = acc[mi][2][nj][q] + bc[3 * HH + c];
                    const float nn = tanhf(in_ + rr * ghn);
                    hv[cc] = (1.0f - zz) * nn + zz * (cc ? hp.y : hp.x);
                }
                float2 ho; ho.x = hv[0]; ho.y = hv[1];
                *(float2*)&h_out[(size_t)m * HH + cb] = ho;
                __nv_bfloat162 vhi, vlo;
                vhi.x = __float2bfloat16_rn(hv[0]);
                vlo.x = __float2bfloat16_rn(hv[0] - __bfloat162float(vhi.x));
                vhi.y = __float2bfloat16_rn(hv[1]);
                vlo.y = __float2bfloat16_rn(hv[1] - __bfloat162float(vhi.y));
                *(__nv_bfloat162*)&hhi_o[(size_t)m * HH + cb] = vhi;
                *(__nv_bfloat162*)&hlo_o[(size_t)m * HH + cb] = vlo;
            }
        }
}

// ---------------- fp32 base GEMM: g_gibase = h_T @ W_ih_dec[:, :512]^T + b_ih_dec ----------------
__global__ __launch_bounds__(256) void base_kernel(const float* __restrict__ W,
                                                   const float* __restrict__ b_ih) {
    __shared__ float As_[16][68];
    __shared__ float Ws_[16][196];
    __shared__ float bihs[192];
    const float* __restrict__ h_in = g_h[0];
    const int tid = threadIdx.x;
    const int tx = tid & 15, ty = tid >> 4;
    const int m0 = blockIdx.x * 64, j0 = blockIdx.y * 64;
    if (tid < 192) bihs[tid] = b_ih[(tid >> 6) * HH + j0 + (tid & 63)];

    float acc[4][12];
#pragma unroll
    for (int i = 0; i < 4; i++)
#pragma unroll
        for (int j = 0; j < 12; j++) acc[i][j] = 0.0f;
    const int r = tid >> 2, kq = (tid & 3) << 2;
    for (int k0 = 0; k0 < HH; k0 += 16) {
        const float4 av  = *(const float4*)(h_in + (size_t)(m0 + r) * HH + k0 + kq);
        const float4 wv0 = *(const float4*)(W + (size_t)(j0 + r) * 528 + k0 + kq);
        const float4 wv1 = *(const float4*)(W + (size_t)(HH + j0 + r) * 528 + k0 + kq);
        const float4 wv2 = *(const float4*)(W + (size_t)(2 * HH + j0 + r) * 528 + k0 + kq);
        __syncthreads();
        As_[kq + 0][r] = av.x; As_[kq + 1][r] = av.y; As_[kq + 2][r] = av.z; As_[kq + 3][r] = av.w;
        Ws_[kq + 0][r] = wv0.x; Ws_[kq + 1][r] = wv0.y; Ws_[kq + 2][r] = wv0.z; Ws_[kq + 3][r] = wv0.w;
        Ws_[kq + 0][64 + r] = wv1.x; Ws_[kq + 1][64 + r] = wv1.y; Ws_[kq + 2][64 + r] = wv1.z; Ws_[kq + 3][64 + r] = wv1.w;
        Ws_[kq + 0][128 + r] = wv2.x; Ws_[kq + 1][128 + r] = wv2.y; Ws_[kq + 2][128 + r] = wv2.z; Ws_[kq + 3][128 + r] = wv2.w;
        __syncthreads();
#pragma unroll
        for (int kk = 0; kk < 16; kk++) {
            const float4 a = *(const float4*)&As_[kk][ty << 2];
            const float4 b0 = *(const float4*)&Ws_[kk][tx << 2];
            const float4 b1 = *(const float4*)&Ws_[kk][64 + (tx << 2)];
            const float4 b2 = *(const float4*)&Ws_[kk][128 + (tx << 2)];
            const float am[4] = {a.x, a.y, a.z, a.w};
            const float bn[12] = {b0.x, b0.y, b0.z, b0.w, b1.x, b1.y, b1.z, b1.w,
                                  b2.x, b2.y, b2.z, b2.w};
#pragma unroll
            for (int i = 0; i < 4; i++)
#pragma unroll
                for (int j = 0; j < 12; j++) acc[i][j] += am[i] * bn[j];
        }
    }
    const int c = tx << 2;
#pragma unroll
    for (int i = 0; i < 4; i++) {
        const int row = m0 + (ty << 2) + i;
#pragma unroll
        for (int g = 0; g < 3; g++) {
            float4 o;
            o.x = acc[i][g * 4 + 0] + bihs[g * 64 + c + 0];
            o.y = acc[i][g * 4 + 1] + bihs[g * 64 + c + 1];
            o.z = acc[i][g * 4 + 2] + bihs[g * 64 + c + 2];
            o.w = acc[i][g * 4 + 3] + bihs[g * 64 + c + 3];
            *(float4*)&g_gibase[(size_t)row * GG + g * HH + j0 + c] = o;
        }
    }
}

__global__ void pred_kernel(int par, const float* __restrict__ Wd,
                            const float* __restrict__ bd, float* __restrict__ out, int t) {
    const int warp = blockIdx.x * (blockDim.x >> 5) + (threadIdx.x >> 5);
    const int lane = threadIdx.x & 31;
    const float* __restrict__ h = g_h[par] + (size_t)warp * HH;
    float s = 0.0f;
#pragma unroll
    for (int k = lane; k < HH; k += 32) s += h[k] * Wd[k];
#pragma unroll
    for (int off = 16; off; off >>= 1) s += __shfl_down_sync(0xffffffffu, s, off);
    if (lane == 0) out[warp * TDEC + t] = s + bd[0];
}

extern "C" void kernel_launch(void* const* d_in, const int* in_sizes, int n_in,
                              void* d_out, int out_size) {
    const float* lag      = (const float*)d_in[0];
    const float* curr     = (const float*)d_in[1];
    const float* W_ih_enc = (const float*)d_in[2];
    const float* W_hh_enc = (const float*)d_in[3];
    const float* b_ih_enc = (const float*)d_in[4];
    const float* b_hh_enc = (const float*)d_in[5];
    const float* W_ih_dec = (const float*)d_in[6];
    const float* W_hh_dec = (const float*)d_in[7];
    const float* b_ih_dec = (const float*)d_in[8];
    const float* b_hh_dec = (const float*)d_in[9];
    const float* W_dense  = (const float*)d_in[10];
    const float* b_dense  = (const float*)d_in[11];
    float* out = (float*)d_out;

    prep_B_kernel<<<1024, 256>>>(W_hh_enc, W_ih_enc, W_hh_dec, W_ih_dec);
    prep_Bn_kernel<<<64, 256>>>(W_ih_enc, W_ih_dec);
    prep_x_kernel<<<1024, 256>>>(lag, curr);
    prep_bc_kernel<<<2, 256>>>(b_ih_enc, b_hh_enc, b_ih_dec, b_hh_dec);
    zero_h_kernel<<<256, 256>>>(0);

    const dim3 grid(16, 8);
    int p = 0;
    for (int t = 0; t < TENC; t++) {
        mma_step<0><<<grid, 256>>>(p, p ^ 1, t);
        p ^= 1;
    }
    // p == 0: h_T in g_h[0]
    base_kernel<<<grid, 256>>>(W_ih_dec, b_ih_dec);
    zero_h_kernel<<<256, 256>>>(1);
    int q = 1;
    for (int t = 0; t < TDEC; t++) {
        mma_step<1><<<grid, 256>>>(q, q ^ 1, t);
        q ^= 1;
        pred_kernel<<<128, 256>>>(q, W_dense, b_dense, out, t);
    }
}

// round 8
// speedup vs baseline: 1.5514x; 1.0568x over previous
#include <cuda_runtime.h>
#include <cuda_bf16.h>
#include <math.h>
#include <stdint.h>

#define BB   1024
#define HH   512
#define GG   1536
#define KE   528      // 512 h + 16 input ext
#define NCH  33       // K chunks of 16
#define TENC 168
#define TDEC 24
#define NSTG 4        // cp.async pipeline stages
#define STGB 16384    // bytes per stage: A 4KB + B 12KB
#define SMEM_DYN (NSTG * STGB + 1024)

// ---------------- persistent device state ----------------
__device__ float g_h[2][BB * HH];
__device__ __align__(16) __nv_bfloat16 g_hhi[2][BB * HH];
__device__ __align__(16) __nv_bfloat16 g_hlo[2][BB * HH];
__device__ float g_gibase[BB * GG];
__device__ __align__(16) __nv_bfloat16 g_B[2][2][GG * KE];   // [enc/dec][hi/lo]
__device__ __align__(16) __nv_bfloat16 g_Bn[2][2][HH * 16];  // gate-n input weights
__device__ __align__(16) __nv_bfloat16 g_xe[2][TENC * BB * 16];
__device__ __align__(16) __nv_bfloat16 g_xd[2][TDEC * BB * 16];
__device__ float g_bc[2][4 * HH];   // combined biases

__device__ __forceinline__ float sigmoidf_(float x) { return 1.0f / (1.0f + expf(-x)); }

__device__ __forceinline__ void ldm4(uint32_t r[4], uint32_t a) {
    asm volatile("ldmatrix.sync.aligned.m8n8.x4.shared.b16 {%0,%1,%2,%3}, [%4];"
                 : "=r"(r[0]), "=r"(r[1]), "=r"(r[2]), "=r"(r[3]) : "r"(a));
}
__device__ __forceinline__ void ldm4p(uint32_t r[4], const __nv_bfloat16* p) {
    uint32_t a = (uint32_t)__cvta_generic_to_shared(p);
    asm volatile("ldmatrix.sync.aligned.m8n8.x4.shared.b16 {%0,%1,%2,%3}, [%4];"
                 : "=r"(r[0]), "=r"(r[1]), "=r"(r[2]), "=r"(r[3]) : "r"(a));
}
__device__ __forceinline__ void mmab(float* d, const uint32_t* a, uint32_t b0, uint32_t b1) {
    asm volatile(
        "mma.sync.aligned.m16n8k16.row.col.f32.bf16.bf16.f32 "
        "{%0,%1,%2,%3},{%4,%5,%6,%7},{%8,%9},{%0,%1,%2,%3};"
        : "+f"(d[0]), "+f"(d[1]), "+f"(d[2]), "+f"(d[3])
        : "r"(a[0]), "r"(a[1]), "r"(a[2]), "r"(a[3]), "r"(b0), "r"(b1));
}
__device__ __forceinline__ void cpa16(uint32_t dst, const __nv_bfloat16* src) {
    asm volatile("cp.async.cg.shared.global [%0], [%1], 16;" :: "r"(dst), "l"(src));
}
__device__ __forceinline__ void cpa16p(const __nv_bfloat16* dst, const __nv_bfloat16* src) {
    uint32_t d = (uint32_t)__cvta_generic_to_shared(dst);
    asm volatile("cp.async.cg.shared.global [%0], [%1], 16;" :: "r"(d), "l"(src));
}
#define CP_COMMIT() asm volatile("cp.async.commit_group;")
#define CP_WAIT2()  asm volatile("cp.async.wait_group 2;")

// ---------------- prep kernels (once per launch) ----------------
__global__ void prep_B_kernel(const float* __restrict__ Whe, const float* __restrict__ Wie,
                              const float* __restrict__ Whd, const float* __restrict__ Wid) {
    for (int idx = blockIdx.x * blockDim.x + threadIdx.x; idx < 2 * GG * KE;
         idx += gridDim.x * blockDim.x) {
        const int which = idx / (GG * KE), r = idx - which * (GG * KE);
        const int G = r / KE, k = r - G * KE;
        float w;
        if (which == 0)
            w = (k < 512) ? Whe[(size_t)G * 512 + k]
                          : ((G < 1024 && (k - 512) < 8) ? Wie[G * 8 + (k - 512)] : 0.0f);
        else
            w = (k < 512) ? Whd[(size_t)G * 512 + k]
                          : ((G < 1024) ? Wid[(size_t)G * 528 + k] : 0.0f);
        const __nv_bfloat16 hi = __float2bfloat16_rn(w);
        g_B[which][0][r] = hi;
        g_B[which][1][r] = __float2bfloat16_rn(w - __bfloat162float(hi));
    }
}
__global__ void prep_Bn_kernel(const float* __restrict__ Wie, const float* __restrict__ Wid) {
    for (int idx = blockIdx.x * blockDim.x + threadIdx.x; idx < 2 * HH * 16;
         idx += gridDim.x * blockDim.x) {
        const int which = idx / (HH * 16), r = idx - which * (HH * 16);
        const int j = r >> 4, e = r & 15;
        float w;
        if (which == 0) w = (e < 8) ? Wie[(1024 + j) * 8 + e] : 0.0f;
        else            w = Wid[(size_t)(1024 + j) * 528 + 512 + e];
        const __nv_bfloat16 hi = __float2bfloat16_rn(w);
        g_Bn[which][0][r] = hi;
        g_Bn[which][1][r] = __float2bfloat16_rn(w - __bfloat162float(hi));
    }
}
__global__ void prep_x_kernel(const float* __restrict__ lag, const float* __restrict__ curr) {
    const int NE = TENC * BB * 16;
    for (int idx = blockIdx.x * blockDim.x + threadIdx.x; idx < NE + TDEC * BB * 16;
         idx += gridDim.x * blockDim.x) {
        if (idx < NE) {
            const int e = idx & 15;
            const float v = (e < 8) ? lag[(idx >> 4) * 8 + e] : 0.0f;
            const __nv_bfloat16 hi = __float2bfloat16_rn(v);
            g_xe[0][idx] = hi;
            g_xe[1][idx] = __float2bfloat16_rn(v - __bfloat162float(hi));
        } else {
            const int r = idx - NE;
            const float v = curr[r];
            const __nv_bfloat16 hi = __float2bfloat16_rn(v);
            g_xd[0][r] = hi;
            g_xd[1][r] = __float2bfloat16_rn(v - __bfloat162float(hi));
        }
    }
}
__global__ void prep_bc_kernel(const float* __restrict__ bie, const float* __restrict__ bhe,
                               const float* __restrict__ bid, const float* __restrict__ bhd) {
    for (int c = blockIdx.x * blockDim.x + threadIdx.x; c < HH;
         c += gridDim.x * blockDim.x) {
        g_bc[0][c]          = bie[c] + bhe[c];
        g_bc[0][HH + c]     = bie[512 + c] + bhe[512 + c];
        g_bc[0][2 * HH + c] = bie[1024 + c];
        g_bc[0][3 * HH + c] = bhe[1024 + c];
        g_bc[1][c]          = bhd[c];
        g_bc[1][HH + c]     = bhd[512 + c];
        g_bc[1][2 * HH + c] = 0.0f;
        g_bc[1][3 * HH + c] = bhd[1024 + c];
    }
}
__global__ void zero_h_kernel(int buf) {
    for (int i = blockIdx.x * blockDim.x + threadIdx.x; i < BB * HH;
         i += gridDim.x * blockDim.x) {
        g_h[buf][i] = 0.0f;
        g_hhi[buf][i] = __float2bfloat16_rn(0.0f);
        g_hlo[buf][i] = __float2bfloat16_rn(0.0f);
    }
}

// ---------------- main tensor-core step kernel ----------------
// Tile: M=64 (batch) x 64 hidden cols x 3 gates, K=528 in 33 chunks of 16.
// 4-stage cp.async pipeline, one __syncthreads per chunk.
// Stage layout (16KB): A at sp*2048 + hf*1024 + row*16 (sp=hi/lo, hf=k-half, row 0..63)
//                      B at 4096 + sp*6144 + hf*3072 + row*16 (row 0..191 = gate*64+col)
template <int DEC>
__global__ __launch_bounds__(256) void mma_step(int pi, int po, int t) {
    extern __shared__ char dsm[];
    __shared__ __align__(16) __nv_bfloat16 Bn[2][2][64][8];   // [split][khalf][row][8]

    const int tid = threadIdx.x;
    const int w = tid >> 5, l = tid & 31;
    const int m0 = blockIdx.x * 64, j0 = blockIdx.y * 64;

    uint32_t dbase = (uint32_t)__cvta_generic_to_shared(dsm);
    dbase = (dbase + 1023) & ~1023u;

    const __nv_bfloat16* __restrict__ Ahi_g = g_hhi[pi];
    const __nv_bfloat16* __restrict__ Alo_g = g_hlo[pi];
    const __nv_bfloat16* __restrict__ Bhi_g = g_B[DEC][0];
    const __nv_bfloat16* __restrict__ Blo_g = g_B[DEC][1];
    const __nv_bfloat16* __restrict__ xhi = (DEC ? g_xd[0] : g_xe[0]) + t * BB * 16;
    const __nv_bfloat16* __restrict__ xlo = (DEC ? g_xd[1] : g_xe[1]) + t * BB * 16;

    // Bn tile (joins group 0)
    {
        const int sp = tid >> 7, rh = tid & 127, row = rh >> 1, hf = rh & 1;
        cpa16p(&Bn[sp][hf][row][0], &g_Bn[DEC][sp][(j0 + row) * 16 + hf * 8]);
    }

    auto load_chunk = [&](int ch, int s) {
        const int k0 = ch * 16;
        const uint32_t sb = dbase + s * STGB;
        {   // A: 256 transfers
            const int sp = tid >> 7, rh = tid & 127, row = rh >> 1, hf = rh & 1;
            const __nv_bfloat16* src;
            if (ch < 32) src = (sp ? Alo_g : Ahi_g) + (size_t)(m0 + row) * HH + k0 + hf * 8;
            else         src = (sp ? xlo : xhi) + (size_t)(m0 + row) * 16 + hf * 8;
            cpa16(sb + sp * 2048 + hf * 1024 + row * 16, src);
        }
#pragma unroll
        for (int j = 0; j < 3; j++) {   // B: 768 transfers
            const int i = j * 256 + tid;
            const int sp = i / 384, rem = i - sp * 384;
            const int row = rem >> 1, hf = rem & 1;
            const int G = (row >> 6) * HH + j0 + (row & 63);
            cpa16(sb + 4096 + sp * 6144 + hf * 3072 + row * 16,
                  (sp ? Blo_g : Bhi_g) + (size_t)G * KE + k0 + hf * 8);
        }
    };

    float acc[2][3][2][4];    // [mi][gate][nj][quad]
    float accn[2][2][4];
#pragma unroll
    for (int a = 0; a < 2; a++)
#pragma unroll
        for (int g = 0; g < 3; g++)
#pragma unroll
            for (int b = 0; b < 2; b++)
#pragma unroll
                for (int q = 0; q < 4; q++) acc[a][g][b][q] = 0.0f;
#pragma unroll
    for (int a = 0; a < 2; a++)
#pragma unroll
        for (int b = 0; b < 2; b++)
#pragma unroll
            for (int q = 0; q < 4; q++) accn[a][b][q] = 0.0f;

    const int mbase = (w >> 2) * 32;     // warp's m offset in tile
    const int nloc  = (w & 3) * 16;      // warp's col offset within 64
    const int arow  = l & 15;            // ldmatrix A row in m16
    const int ahalf = (l >> 4) & 1;
    const int brow  = (l & 7) + ((l >> 4) & 1) * 8;
    const int bhalf = (l >> 3) & 1;

    // prologue: stages 0..2
    load_chunk(0, 0); CP_COMMIT();
    load_chunk(1, 1); CP_COMMIT();
    load_chunk(2, 2); CP_COMMIT();

    for (int ch = 0; ch < NCH; ch++) {
        const int s = ch & (NSTG - 1);
        CP_WAIT2();            // own groups <= ch complete
        __syncthreads();       // all threads' data for stage s visible; stage s-1 free

        // issue loads 3 chunks ahead (into the stage freed by last iteration)
        if (ch + 3 < NCH) load_chunk(ch + 3, (ch + 3) & (NSTG - 1));
        CP_COMMIT();

        const uint32_t sb = dbase + s * STGB;
        uint32_t ahi[2][4], alo[2][4];
#pragma unroll
        for (int mi = 0; mi < 2; mi++) {
            const uint32_t ra = sb + ahalf * 1024 + (mbase + mi * 16 + arow) * 16;
            ldm4(ahi[mi], ra);
            ldm4(alo[mi], ra + 2048);
        }
        uint32_t bhi[3][4], blo[3][4];
#pragma unroll
        for (int g = 0; g < 3; g++) {
            const uint32_t rb = sb + 4096 + bhalf * 3072 + (g * 64 + nloc + brow) * 16;
            ldm4(bhi[g], rb);
            ldm4(blo[g], rb + 6144);
        }
#pragma unroll
        for (int mi = 0; mi < 2; mi++)
#pragma unroll
            for (int g = 0; g < 3; g++)
#pragma unroll
                for (int nj = 0; nj < 2; nj++) {
                    mmab(acc[mi][g][nj], ahi[mi], bhi[g][nj * 2], bhi[g][nj * 2 + 1]);
                    mmab(acc[mi][g][nj], ahi[mi], blo[g][nj * 2], blo[g][nj * 2 + 1]);
                    mmab(acc[mi][g][nj], alo[mi], bhi[g][nj * 2], bhi[g][nj * 2 + 1]);
                }
        if (ch == NCH - 1) {   // gate-n input term (A chunk = x ext)
            uint32_t nhi[4], nlo[4];
            ldm4p(nhi, &Bn[0][bhalf][nloc + brow][0]);
            ldm4p(nlo, &Bn[1][bhalf][nloc + brow][0]);
#pragma unroll
            for (int mi = 0; mi < 2; mi++)
#pragma unroll
                for (int nj = 0; nj < 2; nj++) {
                    mmab(accn[mi][nj], ahi[mi], nhi[nj * 2], nhi[nj * 2 + 1]);
                    mmab(accn[mi][nj], ahi[mi], nlo[nj * 2], nlo[nj * 2 + 1]);
                    mmab(accn[mi][nj], alo[mi], nhi[nj * 2], nhi[nj * 2 + 1]);
                }
        }
    }

    // ---- fused GRU epilogue ----
    const int qr = l >> 2;          // row within m16 half
    const int qc = (l & 3) * 2;     // col pair base within n8
    float* __restrict__ h_out = g_h[po];
    __nv_bfloat16* __restrict__ hhi_o = g_hhi[po];
    __nv_bfloat16* __restrict__ hlo_o = g_hlo[po];
    const float* __restrict__ hprev = g_h[pi];
    const float* __restrict__ bc = g_bc[DEC];

#pragma unroll
    for (int mi = 0; mi < 2; mi++)
#pragma unroll
        for (int nj = 0; nj < 2; nj++) {
            const int cb = j0 + nloc + nj * 8 + qc;   // even
#pragma unroll
            for (int hf = 0; hf < 2; hf++) {
                const int m = m0 + mbase + mi * 16 + qr + hf * 8;
                const float2 hp = *(const float2*)&hprev[(size_t)m * HH + cb];
                float2 gr = {0.f, 0.f}, gz = {0.f, 0.f}, gn = {0.f, 0.f};
                if (DEC) {
                    gr = *(const float2*)&g_gibase[(size_t)m * GG + cb];
                    gz = *(const float2*)&g_gibase[(size_t)m * GG + HH + cb];
                    gn = *(const float2*)&g_gibase[(size_t)m * GG + 2 * HH + cb];
                }
                float hv[2];
#pragma unroll
                for (int cc = 0; cc < 2; cc++) {
                    const int q = hf * 2 + cc, c = cb + cc;
                    const float ibr = cc ? gr.y : gr.x;
                    const float ibz = cc ? gz.y : gz.x;
                    const float ibn = cc ? gn.y : gn.x;
                    const float rr = sigmoidf_(acc[mi][0][nj][q] + ibr + bc[c]);
                    const float zz = sigmoidf_(acc[mi][1][nj][q] + ibz + bc[HH + c]);
                    const float nn = tanhf(accn[mi][nj][q] + ibn + bc[2 * HH + c] +
                                           rr * (acc[mi][2][nj][q] + bc[3 * HH + c]));
                    hv[cc] = (1.0f - zz) * nn + zz * (cc ? hp.y : hp.x);
                }
                float2 ho; ho.x = hv[0]; ho.y = hv[1];
                *(float2*)&h_out[(size_t)m * HH + cb] = ho;
                __nv_bfloat162 vhi, vlo;
                vhi.x = __float2bfloat16_rn(hv[0]);
                vlo.x = __float2bfloat16_rn(hv[0] - __bfloat162float(vhi.x));
                vhi.y = __float2bfloat16_rn(hv[1]);
                vlo.y = __float2bfloat16_rn(hv[1] - __bfloat162float(vhi.y));
                *(__nv_bfloat162*)&hhi_o[(size_t)m * HH + cb] = vhi;
                *(__nv_bfloat162*)&hlo_o[(size_t)m * HH + cb] = vlo;
            }
        }
}

// ---------------- fp32 base GEMM: g_gibase = h_T @ W_ih_dec[:, :512]^T + b_ih_dec ----------------
__global__ __launch_bounds__(256) void base_kernel(const float* __restrict__ W,
                                                   const float* __restrict__ b_ih) {
    __shared__ float As_[16][68];
    __shared__ float Ws_[16][196];
    __shared__ float bihs[192];
    const float* __restrict__ h_in = g_h[0];
    const int tid = threadIdx.x;
    const int tx = tid & 15, ty = tid >> 4;
    const int m0 = blockIdx.x * 64, j0 = blockIdx.y * 64;
    if (tid < 192) bihs[tid] = b_ih[(tid >> 6) * HH + j0 + (tid & 63)];

    float acc[4][12];
#pragma unroll
    for (int i = 0; i < 4; i++)
#pragma unroll
        for (int j = 0; j < 12; j++) acc[i][j] = 0.0f;
    const int r = tid >> 2, kq = (tid & 3) << 2;
    for (int k0 = 0; k0 < HH; k0 += 16) {
        const float4 av  = *(const float4*)(h_in + (size_t)(m0 + r) * HH + k0 + kq);
        const float4 wv0 = *(const float4*)(W + (size_t)(j0 + r) * 528 + k0 + kq);
        const float4 wv1 = *(const float4*)(W + (size_t)(HH + j0 + r) * 528 + k0 + kq);
        const float4 wv2 = *(const float4*)(W + (size_t)(2 * HH + j0 + r) * 528 + k0 + kq);
        __syncthreads();
        As_[kq + 0][r] = av.x; As_[kq + 1][r] = av.y; As_[kq + 2][r] = av.z; As_[kq + 3][r] = av.w;
        Ws_[kq + 0][r] = wv0.x; Ws_[kq + 1][r] = wv0.y; Ws_[kq + 2][r] = wv0.z; Ws_[kq + 3][r] = wv0.w;
        Ws_[kq + 0][64 + r] = wv1.x; Ws_[kq + 1][64 + r] = wv1.y; Ws_[kq + 2][64 + r] = wv1.z; Ws_[kq + 3][64 + r] = wv1.w;
        Ws_[kq + 0][128 + r] = wv2.x; Ws_[kq + 1][128 + r] = wv2.y; Ws_[kq + 2][128 + r] = wv2.z; Ws_[kq + 3][128 + r] = wv2.w;
        __syncthreads();
#pragma unroll
        for (int kk = 0; kk < 16; kk++) {
            const float4 a = *(const float4*)&As_[kk][ty << 2];
            const float4 b0 = *(const float4*)&Ws_[kk][tx << 2];
            const float4 b1 = *(const float4*)&Ws_[kk][64 + (tx << 2)];
            const float4 b2 = *(const float4*)&Ws_[kk][128 + (tx << 2)];
            const float am[4] = {a.x, a.y, a.z, a.w};
            const float bn[12] = {b0.x, b0.y, b0.z, b0.w, b1.x, b1.y, b1.z, b1.w,
                                  b2.x, b2.y, b2.z, b2.w};
#pragma unroll
            for (int i = 0; i < 4; i++)
#pragma unroll
                for (int j = 0; j < 12; j++) acc[i][j] += am[i] * bn[j];
        }
    }
    const int c = tx << 2;
#pragma unroll
    for (int i = 0; i < 4; i++) {
        const int row = m0 + (ty << 2) + i;
#pragma unroll
        for (int g = 0; g < 3; g++) {
            float4 o;
            o.x = acc[i][g * 4 + 0] + bihs[g * 64 + c + 0];
            o.y = acc[i][g * 4 + 1] + bihs[g * 64 + c + 1];
            o.z = acc[i][g * 4 + 2] + bihs[g * 64 + c + 2];
            o.w = acc[i][g * 4 + 3] + bihs[g * 64 + c + 3];
            *(float4*)&g_gibase[(size_t)row * GG + g * HH + j0 + c] = o;
        }
    }
}

__global__ void pred_kernel(int par, const float* __restrict__ Wd,
                            const float* __restrict__ bd, float* __restrict__ out, int t) {
    const int warp = blockIdx.x * (blockDim.x >> 5) + (threadIdx.x >> 5);
    const int lane = threadIdx.x & 31;
    const float* __restrict__ h = g_h[par] + (size_t)warp * HH;
    float s = 0.0f;
#pragma unroll
    for (int k = lane; k < HH; k += 32) s += h[k] * Wd[k];
#pragma unroll
    for (int off = 16; off; off >>= 1) s += __shfl_down_sync(0xffffffffu, s, off);
    if (lane == 0) out[warp * TDEC + t] = s + bd[0];
}

extern "C" void kernel_launch(void* const* d_in, const int* in_sizes, int n_in,
                              void* d_out, int out_size) {
    const float* lag      = (const float*)d_in[0];
    const float* curr     = (const float*)d_in[1];
    const float* W_ih_enc = (const float*)d_in[2];
    const float* W_hh_enc = (const float*)d_in[3];
    const float* b_ih_enc = (const float*)d_in[4];
    const float* b_hh_enc = (const float*)d_in[5];
    const float* W_ih_dec = (const float*)d_in[6];
    const float* W_hh_dec = (const float*)d_in[7];
    const float* b_ih_dec = (const float*)d_in[8];
    const float* b_hh_dec = (const float*)d_in[9];
    const float* W_dense  = (const float*)d_in[10];
    const float* b_dense  = (const float*)d_in[11];
    float* out = (float*)d_out;

    cudaFuncSetAttribute(mma_step<0>, cudaFuncAttributeMaxDynamicSharedMemorySize, SMEM_DYN);
    cudaFuncSetAttribute(mma_step<1>, cudaFuncAttributeMaxDynamicSharedMemorySize, SMEM_DYN);

    prep_B_kernel<<<1024, 256>>>(W_hh_enc, W_ih_enc, W_hh_dec, W_ih_dec);
    prep_Bn_kernel<<<64, 256>>>(W_ih_enc, W_ih_dec);
    prep_x_kernel<<<1024, 256>>>(lag, curr);
    prep_bc_kernel<<<2, 256>>>(b_ih_enc, b_hh_enc, b_ih_dec, b_hh_dec);
    zero_h_kernel<<<256, 256>>>(0);

    const dim3 grid(16, 8);
    int p = 0;
    for (int t = 0; t < TENC; t++) {
        mma_step<0><<<grid, 256, SMEM_DYN>>>(p, p ^ 1, t);
        p ^= 1;
    }
    // p == 0: h_T in g_h[0]
    base_kernel<<<grid, 256>>>(W_ih_dec, b_ih_dec);
    zero_h_kernel<<<256, 256>>>(1);
    int q = 1;
    for (int t = 0; t < TDEC; t++) {
        mma_step<1><<<grid, 256, SMEM_DYN>>>(q, q ^ 1, t);
        q ^= 1;
        pred_kernel<<<128, 256>>>(q, W_dense, b_dense, out, t);
    }
}

// round 9
// speedup vs baseline: 2.4566x; 1.5835x over previous
#include <cuda_runtime.h>
#include <cuda_bf16.h>
#include <math.h>
#include <stdint.h>

#define BB   1024
#define HH   512
#define GG   1536
#define TENC 168
#define TDEC 24
#define NCH  16       // K chunks of 32 (K = 512 exactly; x handled in epilogue)
#define NSTG 4        // cp.async pipeline stages
#define STGB 16384    // per stage: A 4KB (2 splits x [kh2][64][16B]) + B 12KB
#define SMEM_DYN (NSTG * STGB + 1024)

// ---------------- persistent device state ----------------
__device__ float g_h[2][BB * HH];
__device__ __align__(16) signed char g_hq[2][2][BB * HH];   // [buf][hi/lo]
__device__ float g_gibase[BB * GG];
__device__ __align__(16) signed char g_Bq[2][2][GG * HH];   // [enc/dec][hi/lo]
__device__ float g_fB[2][GG];        // per-row dequant factor 1/(127*s1B)
__device__ float g_bc[2][4 * HH];    // combined biases

__device__ __forceinline__ float sigmoidf_(float x) { return 1.0f / (1.0f + expf(-x)); }

__device__ __forceinline__ void ldm4(uint32_t r[4], uint32_t a) {
    asm volatile("ldmatrix.sync.aligned.m8n8.x4.shared.b16 {%0,%1,%2,%3}, [%4];"
                 : "=r"(r[0]), "=r"(r[1]), "=r"(r[2]), "=r"(r[3]) : "r"(a));
}
// s32 += s8 x s8, m16n8k32
__device__ __forceinline__ void mmai(int* d, const uint32_t* a, uint32_t b0, uint32_t b1) {
    asm volatile(
        "mma.sync.aligned.m16n8k32.row.col.s32.s8.s8.s32 "
        "{%0,%1,%2,%3},{%4,%5,%6,%7},{%8,%9},{%0,%1,%2,%3};"
        : "+r"(d[0]), "+r"(d[1]), "+r"(d[2]), "+r"(d[3])
        : "r"(a[0]), "r"(a[1]), "r"(a[2]), "r"(a[3]), "r"(b0), "r"(b1));
}
__device__ __forceinline__ void cpa16(uint32_t dst, const void* src) {
    asm volatile("cp.async.cg.shared.global [%0], [%1], 16;" :: "r"(dst), "l"(src));
}
#define CP_COMMIT() asm volatile("cp.async.commit_group;")
#define CP_WAIT2()  asm volatile("cp.async.wait_group 2;")

// ---------------- prep: per-row int8 quantization of W_hh (+ fB) ----------------
__global__ void prep_Bq_kernel(const float* __restrict__ Whe, const float* __restrict__ Whd) {
    const int gw = blockIdx.x * (blockDim.x >> 5) + (threadIdx.x >> 5);
    if (gw >= 2 * GG) return;
    const int which = gw / GG, G = gw - which * GG;
    const int lane = threadIdx.x & 31;
    const float* __restrict__ W = which ? Whd : Whe;
    const size_t base = (size_t)G * HH;
    float mx = 0.0f;
    for (int k = lane; k < HH; k += 32) mx = fmaxf(mx, fabsf(W[base + k]));
#pragma unroll
    for (int off = 16; off; off >>= 1) mx = fmaxf(mx, __shfl_xor_sync(0xffffffffu, mx, off));
    const float s1 = (mx > 0.0f) ? 127.0f / mx : 1.0f;
    const float inv1 = 1.0f / s1;
    for (int k = lane; k < HH; k += 32) {
        const float w = W[base + k];
        const int hi = __float2int_rn(w * s1);
        const int lo = __float2int_rn((w - (float)hi * inv1) * (s1 * 254.0f));
        g_Bq[which][0][base + k] = (signed char)hi;
        g_Bq[which][1][base + k] = (signed char)lo;
    }
    if (lane == 0) g_fB[which][G] = inv1 * (1.0f / 127.0f);
}
__global__ void prep_bc_kernel(const float* __restrict__ bie, const float* __restrict__ bhe,
                               const float* __restrict__ bid, const float* __restrict__ bhd) {
    for (int c = blockIdx.x * blockDim.x + threadIdx.x; c < HH; c += gridDim.x * blockDim.x) {
        g_bc[0][c]          = bie[c] + bhe[c];
        g_bc[0][HH + c]     = bie[512 + c] + bhe[512 + c];
        g_bc[0][2 * HH + c] = bie[1024 + c];
        g_bc[0][3 * HH + c] = bhe[1024 + c];
        g_bc[1][c]          = bhd[c];
        g_bc[1][HH + c]     = bhd[512 + c];
        g_bc[1][2 * HH + c] = 0.0f;
        g_bc[1][3 * HH + c] = bhd[1024 + c];
    }
}
__global__ void zero_h_kernel(int buf) {
    for (int i = blockIdx.x * blockDim.x + threadIdx.x; i < BB * HH;
         i += gridDim.x * blockDim.x) {
        g_h[buf][i] = 0.0f;
        g_hq[buf][0][i] = 0;
        g_hq[buf][1][i] = 0;
    }
}

// ---------------- main int8 tensor-core step kernel ----------------
// Tile: M=64 x (3 gates x 64 cols), K=512 in 16 chunks of 32, 3-pass int8 split.
// Stage (16KB): A at sp*2048 + kh*1024 + row*16 ; B at 4096 + sp*6144 + kh*3072 + row*16.
template <int DEC, int E>
__global__ __launch_bounds__(256) void mma_step(int pi, int po,
                                                const float* __restrict__ xg,
                                                const float* __restrict__ Wxg) {
    extern __shared__ char dsm[];
    __shared__ float Wxs[192 * 16];
    __shared__ float xs[64 * 16];
    __shared__ float fBs[192];

    const int tid = threadIdx.x;
    const int w = tid >> 5, l = tid & 31;
    const int m0 = blockIdx.x * 64, j0 = blockIdx.y * 64;

    uint32_t dbase = (uint32_t)__cvta_generic_to_shared(dsm);
    dbase = (dbase + 1023) & ~1023u;

    // ---- epilogue constants into smem (plain loads; visible after loop syncs) ----
    if (tid < 192) fBs[tid] = g_fB[DEC][(tid >> 6) * HH + j0 + (tid & 63)];
    for (int idx = tid; idx < 64 * E; idx += 256) xs[idx] = xg[m0 * E + idx];
    for (int idx = tid; idx < 192 * E; idx += 256) {
        const int n = idx / E, e = idx - n * E;
        const int G = (n >> 6) * HH + j0 + (n & 63);
        Wxs[idx] = DEC ? Wxg[(size_t)G * 528 + 512 + e] : Wxg[G * 8 + e];
    }

    const signed char* __restrict__ Ahi_g = g_hq[pi][0];
    const signed char* __restrict__ Alo_g = g_hq[pi][1];
    const signed char* __restrict__ Bhi_g = g_Bq[DEC][0];
    const signed char* __restrict__ Blo_g = g_Bq[DEC][1];

    auto load_chunk = [&](int ch, int s) {
        const int k0 = ch * 32;
        const uint32_t sb = dbase + s * STGB;
        {   // A: 256 x 16B
            const int sp = tid >> 7, rem = tid & 127, row = rem >> 1, kh = rem & 1;
            cpa16(sb + sp * 2048 + kh * 1024 + row * 16,
                  (sp ? Alo_g : Ahi_g) + (size_t)(m0 + row) * HH + k0 + kh * 16);
        }
#pragma unroll
        for (int j = 0; j < 3; j++) {   // B: 768 x 16B
            const int i = j * 256 + tid;
            const int sp = i / 384, rem = i - sp * 384;
            const int row = rem >> 1, kh = rem & 1;
            const int G = (row >> 6) * HH + j0 + (row & 63);
            cpa16(sb + 4096 + sp * 6144 + kh * 3072 + row * 16,
                  (sp ? Blo_g : Bhi_g) + (size_t)G * HH + k0 + kh * 16);
        }
    };

    int P1[2][3][2][4], P2[2][3][2][4];
#pragma unroll
    for (int a = 0; a < 2; a++)
#pragma unroll
        for (int g = 0; g < 3; g++)
#pragma unroll
            for (int b = 0; b < 2; b++)
#pragma unroll
                for (int q = 0; q < 4; q++) { P1[a][g][b][q] = 0; P2[a][g][b][q] = 0; }

    const int mbase = (w >> 2) * 32;
    const int nloc  = (w & 3) * 16;
    const int arow  = l & 15;
    const int ahalf = (l >> 4) & 1;
    const int brow  = (l & 7) + ((l >> 4) & 1) * 8;
    const int bhalf = (l >> 3) & 1;

    load_chunk(0, 0); CP_COMMIT();
    load_chunk(1, 1); CP_COMMIT();
    load_chunk(2, 2); CP_COMMIT();

    for (int ch = 0; ch < NCH; ch++) {
        const int s = ch & (NSTG - 1);
        CP_WAIT2();
        __syncthreads();
        if (ch + 3 < NCH) load_chunk(ch + 3, (ch + 3) & (NSTG - 1));
        CP_COMMIT();

        const uint32_t sb = dbase + s * STGB;
        uint32_t ahi[2][4], alo[2][4];
#pragma unroll
        for (int mi = 0; mi < 2; mi++) {
            const uint32_t ra = sb + ahalf * 1024 + (mbase + mi * 16 + arow) * 16;
            ldm4(ahi[mi], ra);
            ldm4(alo[mi], ra + 2048);
        }
        uint32_t bhi[3][4], blo[3][4];
#pragma unroll
        for (int g = 0; g < 3; g++) {
            const uint32_t rb = sb + 4096 + bhalf * 3072 + (g * 64 + nloc + brow) * 16;
            ldm4(bhi[g], rb);
            ldm4(blo[g], rb + 6144);
        }
#pragma unroll
        for (int mi = 0; mi < 2; mi++)
#pragma unroll
            for (int g = 0; g < 3; g++)
#pragma unroll
                for (int nj = 0; nj < 2; nj++) {
                    mmai(P1[mi][g][nj], ahi[mi], bhi[g][nj * 2], bhi[g][nj * 2 + 1]);
                    mmai(P2[mi][g][nj], ahi[mi], blo[g][nj * 2], blo[g][nj * 2 + 1]);
                    mmai(P2[mi][g][nj], alo[mi], bhi[g][nj * 2], bhi[g][nj * 2 + 1]);
                }
    }
    __syncthreads();   // Wxs/xs/fBs visible (also covered by loop syncs)

    // ---- fused GRU epilogue (dequant + x-GEMM in fp32 + gates + requant) ----
    const int qr = l >> 2;
    const int qc = (l & 3) * 2;
    const float INV254 = 1.0f / 254.0f;
    float* __restrict__ h_out = g_h[po];
    signed char* __restrict__ hq_hi = g_hq[po][0];
    signed char* __restrict__ hq_lo = g_hq[po][1];
    const float* __restrict__ hprev = g_h[pi];
    const float* __restrict__ bc = g_bc[DEC];

#pragma unroll
    for (int mi = 0; mi < 2; mi++)
#pragma unroll
        for (int nj = 0; nj < 2; nj++) {
            const int cl0 = nloc + nj * 8 + qc;
            const int cb = j0 + cl0;
#pragma unroll
            for (int hf = 0; hf < 2; hf++) {
                const int ml = mbase + mi * 16 + qr + hf * 8;
                const int m = m0 + ml;
                const float2 hp = *(const float2*)&hprev[(size_t)m * HH + cb];
                float2 gr = {0.f, 0.f}, gz = {0.f, 0.f}, gn = {0.f, 0.f};
                if (DEC) {
                    gr = *(const float2*)&g_gibase[(size_t)m * GG + cb];
                    gz = *(const float2*)&g_gibase[(size_t)m * GG + HH + cb];
                    gn = *(const float2*)&g_gibase[(size_t)m * GG + 2 * HH + cb];
                }
                float hv[2]; int hqi[2], hql[2];
#pragma unroll
                for (int cc = 0; cc < 2; cc++) {
                    const int q = hf * 2 + cc, cl = cl0 + cc, c = cb + cc;
                    const float pr = ((float)P1[mi][0][nj][q] + (float)P2[mi][0][nj][q] * INV254) * fBs[cl];
                    const float pz = ((float)P1[mi][1][nj][q] + (float)P2[mi][1][nj][q] * INV254) * fBs[64 + cl];
                    const float pn = ((float)P1[mi][2][nj][q] + (float)P2[mi][2][nj][q] * INV254) * fBs[128 + cl];
                    float xr = 0.f, xz = 0.f, xn = 0.f;
#pragma unroll
                    for (int e = 0; e < E; e++) {
                        const float xv = xs[ml * E + e];
                        xr += xv * Wxs[cl * E + e];
                        xz += xv * Wxs[(64 + cl) * E + e];
                        xn += xv * Wxs[(128 + cl) * E + e];
                    }
                    const float ir = (DEC ? (cc ? gr.y : gr.x) : 0.f) + xr;
                    const float iz = (DEC ? (cc ? gz.y : gz.x) : 0.f) + xz;
                    const float in0 = (DEC ? (cc ? gn.y : gn.x) : 0.f) + xn;
                    const float rr = sigmoidf_(pr + ir + bc[c]);
                    const float zz = sigmoidf_(pz + iz + bc[HH + c]);
                    const float nn = tanhf(in0 + bc[2 * HH + c] + rr * (pn + bc[3 * HH + c]));
                    const float h = (1.0f - zz) * nn + zz * (cc ? hp.y : hp.x);
                    hv[cc] = h;
                    const int hi = __float2int_rn(h * 127.0f);
                    hqi[cc] = hi;
                    hql[cc] = __float2int_rn((h - (float)hi * (1.0f / 127.0f)) * 32258.0f);
                }
                float2 ho; ho.x = hv[0]; ho.y = hv[1];
                *(float2*)&h_out[(size_t)m * HH + cb] = ho;
                *(char2*)&hq_hi[(size_t)m * HH + cb] = make_char2((char)hqi[0], (char)hqi[1]);
                *(char2*)&hq_lo[(size_t)m * HH + cb] = make_char2((char)hql[0], (char)hql[1]);
            }
        }
}

// ---------------- fp32 base GEMM: g_gibase = h_T @ W_ih_dec[:, :512]^T + b_ih_dec ----------------
__global__ __launch_bounds__(256) void base_kernel(const float* __restrict__ W,
                                                   const float* __restrict__ b_ih) {
    __shared__ float As_[16][68];
    __shared__ float Ws_[16][196];
    __shared__ float bihs[192];
    const float* __restrict__ h_in = g_h[0];
    const int tid = threadIdx.x;
    const int tx = tid & 15, ty = tid >> 4;
    const int m0 = blockIdx.x * 64, j0 = blockIdx.y * 64;
    if (tid < 192) bihs[tid] = b_ih[(tid >> 6) * HH + j0 + (tid & 63)];

    float acc[4][12];
#pragma unroll
    for (int i = 0; i < 4; i++)
#pragma unroll
        for (int j = 0; j < 12; j++) acc[i][j] = 0.0f;
    const int r = tid >> 2, kq = (tid & 3) << 2;
    for (int k0 = 0; k0 < HH; k0 += 16) {
        const float4 av  = *(const float4*)(h_in + (size_t)(m0 + r) * HH + k0 + kq);
        const float4 wv0 = *(const float4*)(W + (size_t)(j0 + r) * 528 + k0 + kq);
        const float4 wv1 = *(const float4*)(W + (size_t)(HH + j0 + r) * 528 + k0 + kq);
        const float4 wv2 = *(const float4*)(W + (size_t)(2 * HH + j0 + r) * 528 + k0 + kq);
        __syncthreads();
        As_[kq + 0][r] = av.x; As_[kq + 1][r] = av.y; As_[kq + 2][r] = av.z; As_[kq + 3][r] = av.w;
        Ws_[kq + 0][r] = wv0.x; Ws_[kq + 1][r] = wv0.y; Ws_[kq + 2][r] = wv0.z; Ws_[kq + 3][r] = wv0.w;
        Ws_[kq + 0][64 + r] = wv1.x; Ws_[kq + 1][64 + r] = wv1.y; Ws_[kq + 2][64 + r] = wv1.z; Ws_[kq + 3][64 + r] = wv1.w;
        Ws_[kq + 0][128 + r] = wv2.x; Ws_[kq + 1][128 + r] = wv2.y; Ws_[kq + 2][128 + r] = wv2.z; Ws_[kq + 3][128 + r] = wv2.w;
        __syncthreads();
#pragma unroll
        for (int kk = 0; kk < 16; kk++) {
            const float4 a = *(const float4*)&As_[kk][ty << 2];
            const float4 b0 = *(const float4*)&Ws_[kk][tx << 2];
            const float4 b1 = *(const float4*)&Ws_[kk][64 + (tx << 2)];
            const float4 b2 = *(const float4*)&Ws_[kk][128 + (tx << 2)];
            const float am[4] = {a.x, a.y, a.z, a.w};
            const float bn[12] = {b0.x, b0.y, b0.z, b0.w, b1.x, b1.y, b1.z, b1.w,
                                  b2.x, b2.y, b2.z, b2.w};
#pragma unroll
            for (int i = 0; i < 4; i++)
#pragma unroll
                for (int j = 0; j < 12; j++) acc[i][j] += am[i] * bn[j];
        }
    }
    const int c = tx << 2;
#pragma unroll
    for (int i = 0; i < 4; i++) {
        const int row = m0 + (ty << 2) + i;
#pragma unroll
        for (int g = 0; g < 3; g++) {
            float4 o;
            o.x = acc[i][g * 4 + 0] + bihs[g * 64 + c + 0];
            o.y = acc[i][g * 4 + 1] + bihs[g * 64 + c + 1];
            o.z = acc[i][g * 4 + 2] + bihs[g * 64 + c + 2];
            o.w = acc[i][g * 4 + 3] + bihs[g * 64 + c + 3];
            *(float4*)&g_gibase[(size_t)row * GG + g * HH + j0 + c] = o;
        }
    }
}

__global__ void pred_kernel(int par, const float* __restrict__ Wd,
                            const float* __restrict__ bd, float* __restrict__ out, int t) {
    const int warp = blockIdx.x * (blockDim.x >> 5) + (threadIdx.x >> 5);
    const int lane = threadIdx.x & 31;
    const float* __restrict__ h = g_h[par] + (size_t)warp * HH;
    float s = 0.0f;
#pragma unroll
    for (int k = lane; k < HH; k += 32) s += h[k] * Wd[k];
#pragma unroll
    for (int off = 16; off; off >>= 1) s += __shfl_down_sync(0xffffffffu, s, off);
    if (lane == 0) out[warp * TDEC + t] = s + bd[0];
}

extern "C" void kernel_launch(void* const* d_in, const int* in_sizes, int n_in,
                              void* d_out, int out_size) {
    const float* lag      = (const float*)d_in[0];
    const float* curr     = (const float*)d_in[1];
    const float* W_ih_enc = (const float*)d_in[2];
    const float* W_hh_enc = (const float*)d_in[3];
    const float* b_ih_enc = (const float*)d_in[4];
    const float* b_hh_enc = (const float*)d_in[5];
    const float* W_ih_dec = (const float*)d_in[6];
    const float* W_hh_dec = (const float*)d_in[7];
    const float* b_ih_dec = (const float*)d_in[8];
    const float* b_hh_dec = (const float*)d_in[9];
    const float* W_dense  = (const float*)d_in[10];
    const float* b_dense  = (const float*)d_in[11];
    float* out = (float*)d_out;

    cudaFuncSetAttribute(mma_step<0, 8>, cudaFuncAttributeMaxDynamicSharedMemorySize, SMEM_DYN);
    cudaFuncSetAttribute(mma_step<1, 16>, cudaFuncAttributeMaxDynamicSharedMemorySize, SMEM_DYN);

    prep_Bq_kernel<<<384, 256>>>(W_hh_enc, W_hh_dec);
    prep_bc_kernel<<<2, 256>>>(b_ih_enc, b_hh_enc, b_ih_dec, b_hh_dec);
    zero_h_kernel<<<256, 256>>>(0);

    const dim3 grid(16, 8);
    int p = 0;
    for (int t = 0; t < TENC; t++) {
        mma_step<0, 8><<<grid, 256, SMEM_DYN>>>(p, p ^ 1, lag + (size_t)t * BB * 8, W_ih_enc);
        p ^= 1;
    }
    // 168 even -> h_T in g_h[0]
    base_kernel<<<grid, 256>>>(W_ih_dec, b_ih_dec);
    zero_h_kernel<<<256, 256>>>(1);
    int q = 1;
    for (int t = 0; t < TDEC; t++) {
        mma_step<1, 16><<<grid, 256, SMEM_DYN>>>(q, q ^ 1, curr + (size_t)t * BB * 16, W_ih_dec);
        q ^= 1;
        pred_kernel<<<128, 256>>>(q, W_dense, b_dense, out, t);
    }
}

// round 10
// speedup vs baseline: 2.5664x; 1.0447x over previous
#include <cuda_runtime.h>
#include <cuda_bf16.h>
#include <math.h>
#include <stdint.h>

#define BB   1024
#define HH   512
#define GG   1536
#define TENC 168
#define TDEC 24
#define NCH  16       // K chunks of 32 (K = 512; x handled in epilogue)
#define NSTG 4
#define STGB 16384    // per stage: A 4KB + B 12KB
#define SMEM_DYN (NSTG * STGB + 1024)
#define NT   512      // 16 warps = 4 per SMSP

// ---------------- persistent device state ----------------
__device__ float g_h[2][BB * HH];
__device__ __align__(16) signed char g_hq[2][2][BB * HH];   // [buf][hi/lo]
__device__ float g_gibase[BB * GG];
__device__ __align__(16) signed char g_Bq[2][2][GG * HH];   // [enc/dec][hi/lo]
__device__ float g_fB[2][GG];
__device__ float g_bc[2][4 * HH];

__device__ __forceinline__ float sigmoidf_(float x) { return 1.0f / (1.0f + expf(-x)); }

__device__ __forceinline__ void ldm4(uint32_t r[4], uint32_t a) {
    asm volatile("ldmatrix.sync.aligned.m8n8.x4.shared.b16 {%0,%1,%2,%3}, [%4];"
                 : "=r"(r[0]), "=r"(r[1]), "=r"(r[2]), "=r"(r[3]) : "r"(a));
}
__device__ __forceinline__ void mmai(int* d, const uint32_t* a, uint32_t b0, uint32_t b1) {
    asm volatile(
        "mma.sync.aligned.m16n8k32.row.col.s32.s8.s8.s32 "
        "{%0,%1,%2,%3},{%4,%5,%6,%7},{%8,%9},{%0,%1,%2,%3};"
        : "+r"(d[0]), "+r"(d[1]), "+r"(d[2]), "+r"(d[3])
        : "r"(a[0]), "r"(a[1]), "r"(a[2]), "r"(a[3]), "r"(b0), "r"(b1));
}
__device__ __forceinline__ void cpa16(uint32_t dst, const void* src) {
    asm volatile("cp.async.cg.shared.global [%0], [%1], 16;" :: "r"(dst), "l"(src));
}
#define CP_COMMIT() asm volatile("cp.async.commit_group;")
#define CP_WAIT2()  asm volatile("cp.async.wait_group 2;")

// ---------------- prep: per-row int8 quantization of W_hh ----------------
__global__ void prep_Bq_kernel(const float* __restrict__ Whe, const float* __restrict__ Whd) {
    const int gw = blockIdx.x * (blockDim.x >> 5) + (threadIdx.x >> 5);
    if (gw >= 2 * GG) return;
    const int which = gw / GG, G = gw - which * GG;
    const int lane = threadIdx.x & 31;
    const float* __restrict__ W = which ? Whd : Whe;
    const size_t base = (size_t)G * HH;
    float mx = 0.0f;
    for (int k = lane; k < HH; k += 32) mx = fmaxf(mx, fabsf(W[base + k]));
#pragma unroll
    for (int off = 16; off; off >>= 1) mx = fmaxf(mx, __shfl_xor_sync(0xffffffffu, mx, off));
    const float s1 = (mx > 0.0f) ? 127.0f / mx : 1.0f;
    const float inv1 = 1.0f / s1;
    for (int k = lane; k < HH; k += 32) {
        const float w = W[base + k];
        const int hi = __float2int_rn(w * s1);
        const int lo = __float2int_rn((w - (float)hi * inv1) * (s1 * 254.0f));
        g_Bq[which][0][base + k] = (signed char)hi;
        g_Bq[which][1][base + k] = (signed char)lo;
    }
    if (lane == 0) g_fB[which][G] = inv1 * (1.0f / 127.0f);
}
__global__ void prep_bc_kernel(const float* __restrict__ bie, const float* __restrict__ bhe,
                               const float* __restrict__ bid, const float* __restrict__ bhd) {
    for (int c = blockIdx.x * blockDim.x + threadIdx.x; c < HH; c += gridDim.x * blockDim.x) {
        g_bc[0][c]          = bie[c] + bhe[c];
        g_bc[0][HH + c]     = bie[512 + c] + bhe[512 + c];
        g_bc[0][2 * HH + c] = bie[1024 + c];
        g_bc[0][3 * HH + c] = bhe[1024 + c];
        g_bc[1][c]          = bhd[c];
        g_bc[1][HH + c]     = bhd[512 + c];
        g_bc[1][2 * HH + c] = 0.0f;
        g_bc[1][3 * HH + c] = bhd[1024 + c];
    }
}
__global__ void zero_h_kernel(int buf) {
    for (int i = blockIdx.x * blockDim.x + threadIdx.x; i < BB * HH;
         i += gridDim.x * blockDim.x) {
        g_h[buf][i] = 0.0f;
        g_hq[buf][0][i] = 0;
        g_hq[buf][1][i] = 0;
    }
}

// ---------------- main int8 tensor-core step kernel ----------------
// 512 threads, 16 warps: 4 m-warps x 4 n-warps, each warp a 16x16 patch x 3 gates.
// Tile: M=64 x (3 gates x 64 cols), K=512 in 16 chunks of 32, 3-pass int8 split.
template <int DEC, int E>
__global__ __launch_bounds__(NT) void mma_step(int pi, int po,
                                               const float* __restrict__ xg,
                                               const float* __restrict__ Wxg) {
    extern __shared__ char dsm[];
    __shared__ float Wxs[192 * 16];
    __shared__ float xs[64 * 16];
    __shared__ float fBs[192];

    const int tid = threadIdx.x;
    const int w = tid >> 5, l = tid & 31;
    const int m0 = blockIdx.x * 64, j0 = blockIdx.y * 64;

    uint32_t dbase = (uint32_t)__cvta_generic_to_shared(dsm);
    dbase = (dbase + 1023) & ~1023u;

    // epilogue constants
    if (tid < 192) fBs[tid] = g_fB[DEC][(tid >> 6) * HH + j0 + (tid & 63)];
    for (int idx = tid; idx < 64 * E; idx += NT) xs[idx] = xg[m0 * E + idx];
    for (int idx = tid; idx < 192 * E; idx += NT) {
        const int n = idx / E, e = idx - n * E;
        const int G = (n >> 6) * HH + j0 + (n & 63);
        Wxs[idx] = DEC ? Wxg[(size_t)G * 528 + 512 + e] : Wxg[G * 8 + e];
    }

    const signed char* __restrict__ Ahi_g = g_hq[pi][0];
    const signed char* __restrict__ Alo_g = g_hq[pi][1];
    const signed char* __restrict__ Bhi_g = g_Bq[DEC][0];
    const signed char* __restrict__ Blo_g = g_Bq[DEC][1];

    auto load_chunk = [&](int ch, int s) {
        const int k0 = ch * 32;
        const uint32_t sb = dbase + s * STGB;
#pragma unroll
        for (int rep = 0; rep < 2; rep++) {   // 1024 x 16B over 512 threads
            const int i = rep * NT + tid;
            if (i < 256) {                    // A
                const int sp = i >> 7, rem = i & 127, row = rem >> 1, kh = rem & 1;
                cpa16(sb + sp * 2048 + kh * 1024 + row * 16,
                      (sp ? Alo_g : Ahi_g) + (size_t)(m0 + row) * HH + k0 + kh * 16);
            } else {                          // B
                const int j = i - 256;
                const int sp = j / 384, rem = j - sp * 384;
                const int row = rem >> 1, kh = rem & 1;
                const int G = (row >> 6) * HH + j0 + (row & 63);
                cpa16(sb + 4096 + sp * 6144 + kh * 3072 + row * 16,
                      (sp ? Blo_g : Bhi_g) + (size_t)G * HH + k0 + kh * 16);
            }
        }
    };

    int P1[3][2][4], P2[3][2][4];
#pragma unroll
    for (int g = 0; g < 3; g++)
#pragma unroll
        for (int b = 0; b < 2; b++)
#pragma unroll
            for (int q = 0; q < 4; q++) { P1[g][b][q] = 0; P2[g][b][q] = 0; }

    const int mbase = (w >> 2) * 16;     // m-warp: 16 rows
    const int nloc  = (w & 3) * 16;      // n-warp: 16 cols (per gate)
    const int arow  = l & 15;
    const int ahalf = (l >> 4) & 1;
    const int brow  = (l & 7) + ((l >> 4) & 1) * 8;
    const int bhalf = (l >> 3) & 1;

    load_chunk(0, 0); CP_COMMIT();
    load_chunk(1, 1); CP_COMMIT();
    load_chunk(2, 2); CP_COMMIT();

    for (int ch = 0; ch < NCH; ch++) {
        const int s = ch & (NSTG - 1);
        CP_WAIT2();
        __syncthreads();
        if (ch + 3 < NCH) load_chunk(ch + 3, (ch + 3) & (NSTG - 1));
        CP_COMMIT();

        const uint32_t sb = dbase + s * STGB;
        uint32_t ahi[4], alo[4];
        {
            const uint32_t ra = sb + ahalf * 1024 + (mbase + arow) * 16;
            ldm4(ahi, ra);
            ldm4(alo, ra + 2048);
        }
        uint32_t bhi[3][4], blo[3][4];
#pragma unroll
        for (int g = 0; g < 3; g++) {
            const uint32_t rb = sb + 4096 + bhalf * 3072 + (g * 64 + nloc + brow) * 16;
            ldm4(bhi[g], rb);
            ldm4(blo[g], rb + 6144);
        }
#pragma unroll
        for (int g = 0; g < 3; g++)
#pragma unroll
            for (int nj = 0; nj < 2; nj++) {
                mmai(P1[g][nj], ahi, bhi[g][nj * 2], bhi[g][nj * 2 + 1]);
                mmai(P2[g][nj], ahi, blo[g][nj * 2], blo[g][nj * 2 + 1]);
                mmai(P2[g][nj], alo, bhi[g][nj * 2], bhi[g][nj * 2 + 1]);
            }
    }
    __syncthreads();

    // ---- fused GRU epilogue ----
    const int qr = l >> 2;
    const int qc = (l & 3) * 2;
    const float INV254 = 1.0f / 254.0f;
    float* __restrict__ h_out = g_h[po];
    signed char* __restrict__ hq_hi = g_hq[po][0];
    signed char* __restrict__ hq_lo = g_hq[po][1];
    const float* __restrict__ hprev = g_h[pi];
    const float* __restrict__ bc = g_bc[DEC];

#pragma unroll
    for (int nj = 0; nj < 2; nj++) {
        const int cl0 = nloc + nj * 8 + qc;
        const int cb = j0 + cl0;
#pragma unroll
        for (int hf = 0; hf < 2; hf++) {
            const int ml = mbase + qr + hf * 8;
            const int m = m0 + ml;
            const float2 hp = *(const float2*)&hprev[(size_t)m * HH + cb];
            float2 gr = {0.f, 0.f}, gz = {0.f, 0.f}, gn = {0.f, 0.f};
            if (DEC) {
                gr = *(const float2*)&g_gibase[(size_t)m * GG + cb];
                gz = *(const float2*)&g_gibase[(size_t)m * GG + HH + cb];
                gn = *(const float2*)&g_gibase[(size_t)m * GG + 2 * HH + cb];
            }
            float hv[2]; int hqi[2], hql[2];
#pragma unroll
            for (int cc = 0; cc < 2; cc++) {
                const int q = hf * 2 + cc, cl = cl0 + cc, c = cb + cc;
                const float pr = ((float)P1[0][nj][q] + (float)P2[0][nj][q] * INV254) * fBs[cl];
                const float pz = ((float)P1[1][nj][q] + (float)P2[1][nj][q] * INV254) * fBs[64 + cl];
                const float pn = ((float)P1[2][nj][q] + (float)P2[2][nj][q] * INV254) * fBs[128 + cl];
                float xr = 0.f, xz = 0.f, xn = 0.f;
#pragma unroll
                for (int e = 0; e < E; e++) {
                    const float xv = xs[ml * E + e];
                    xr += xv * Wxs[cl * E + e];
                    xz += xv * Wxs[(64 + cl) * E + e];
                    xn += xv * Wxs[(128 + cl) * E + e];
                }
                const float ir = (DEC ? (cc ? gr.y : gr.x) : 0.f) + xr;
                const float iz = (DEC ? (cc ? gz.y : gz.x) : 0.f) + xz;
                const float in0 = (DEC ? (cc ? gn.y : gn.x) : 0.f) + xn;
                const float rr = sigmoidf_(pr + ir + bc[c]);
                const float zz = sigmoidf_(pz + iz + bc[HH + c]);
                const float nn = tanhf(in0 + bc[2 * HH + c] + rr * (pn + bc[3 * HH + c]));
                const float h = (1.0f - zz) * nn + zz * (cc ? hp.y : hp.x);
                hv[cc] = h;
                const int hi = __float2int_rn(h * 127.0f);
                hqi[cc] = hi;
                hql[cc] = __float2int_rn((h - (float)hi * (1.0f / 127.0f)) * 32258.0f);
            }
            float2 ho; ho.x = hv[0]; ho.y = hv[1];
            *(float2*)&h_out[(size_t)m * HH + cb] = ho;
            *(char2*)&hq_hi[(size_t)m * HH + cb] = make_char2((char)hqi[0], (char)hqi[1]);
            *(char2*)&hq_lo[(size_t)m * HH + cb] = make_char2((char)hql[0], (char)hql[1]);
        }
    }
}

// ---------------- fp32 base GEMM (once) ----------------
__global__ __launch_bounds__(256) void base_kernel(const float* __restrict__ W,
                                                   const float* __restrict__ b_ih) {
    __shared__ float As_[16][68];
    __shared__ float Ws_[16][196];
    __shared__ float bihs[192];
    const float* __restrict__ h_in = g_h[0];
    const int tid = threadIdx.x;
    const int tx = tid & 15, ty = tid >> 4;
    const int m0 = blockIdx.x * 64, j0 = blockIdx.y * 64;
    if (tid < 192) bihs[tid] = b_ih[(tid >> 6) * HH + j0 + (tid & 63)];

    float acc[4][12];
#pragma unroll
    for (int i = 0; i < 4; i++)
#pragma unroll
        for (int j = 0; j < 12; j++) acc[i][j] = 0.0f;
    const int r = tid >> 2, kq = (tid & 3) << 2;
    for (int k0 = 0; k0 < HH; k0 += 16) {
        const float4 av  = *(const float4*)(h_in + (size_t)(m0 + r) * HH + k0 + kq);
        const float4 wv0 = *(const float4*)(W + (size_t)(j0 + r) * 528 + k0 + kq);
        const float4 wv1 = *(const float4*)(W + (size_t)(HH + j0 + r) * 528 + k0 + kq);
        const float4 wv2 = *(const float4*)(W + (size_t)(2 * HH + j0 + r) * 528 + k0 + kq);
        __syncthreads();
        As_[kq + 0][r] = av.x; As_[kq + 1][r] = av.y; As_[kq + 2][r] = av.z; As_[kq + 3][r] = av.w;
        Ws_[kq + 0][r] = wv0.x; Ws_[kq + 1][r] = wv0.y; Ws_[kq + 2][r] = wv0.z; Ws_[kq + 3][r] = wv0.w;
        Ws_[kq + 0][64 + r] = wv1.x; Ws_[kq + 1][64 + r] = wv1.y; Ws_[kq + 2][64 + r] = wv1.z; Ws_[kq + 3][64 + r] = wv1.w;
        Ws_[kq + 0][128 + r] = wv2.x; Ws_[kq + 1][128 + r] = wv2.y; Ws_[kq + 2][128 + r] = wv2.z; Ws_[kq + 3][128 + r] = wv2.w;
        __syncthreads();
#pragma unroll
        for (int kk = 0; kk < 16; kk++) {
            const float4 a = *(const float4*)&As_[kk][ty << 2];
            const float4 b0 = *(const float4*)&Ws_[kk][tx << 2];
            const float4 b1 = *(const float4*)&Ws_[kk][64 + (tx << 2)];
            const float4 b2 = *(const float4*)&Ws_[kk][128 + (tx << 2)];
            const float am[4] = {a.x, a.y, a.z, a.w};
            const float bn[12] = {b0.x, b0.y, b0.z, b0.w, b1.x, b1.y, b1.z, b1.w,
                                  b2.x, b2.y, b2.z, b2.w};
#pragma unroll
            for (int i = 0; i < 4; i++)
#pragma unroll
                for (int j = 0; j < 12; j++) acc[i][j] += am[i] * bn[j];
        }
    }
    const int c = tx << 2;
#pragma unroll
    for (int i = 0; i < 4; i++) {
        const int row = m0 + (ty << 2) + i;
#pragma unroll
        for (int g = 0; g < 3; g++) {
            float4 o;
            o.x = acc[i][g * 4 + 0] + bihs[g * 64 + c + 0];
            o.y = acc[i][g * 4 + 1] + bihs[g * 64 + c + 1];
            o.z = acc[i][g * 4 + 2] + bihs[g * 64 + c + 2];
            o.w = acc[i][g * 4 + 3] + bihs[g * 64 + c + 3];
            *(float4*)&g_gibase[(size_t)row * GG + g * HH + j0 + c] = o;
        }
    }
}

__global__ void pred_kernel(int par, const float* __restrict__ Wd,
                            const float* __restrict__ bd, float* __restrict__ out, int t) {
    const int warp = blockIdx.x * (blockDim.x >> 5) + (threadIdx.x >> 5);
    const int lane = threadIdx.x & 31;
    const float* __restrict__ h = g_h[par] + (size_t)warp * HH;
    float s = 0.0f;
#pragma unroll
    for (int k = lane; k < HH; k += 32) s += h[k] * Wd[k];
#pragma unroll
    for (int off = 16; off; off >>= 1) s += __shfl_down_sync(0xffffffffu, s, off);
    if (lane == 0) out[warp * TDEC + t] = s + bd[0];
}

extern "C" void kernel_launch(void* const* d_in, const int* in_sizes, int n_in,
                              void* d_out, int out_size) {
    const float* lag      = (const float*)d_in[0];
    const float* curr     = (const float*)d_in[1];
    const float* W_ih_enc = (const float*)d_in[2];
    const float* W_hh_enc = (const float*)d_in[3];
    const float* b_ih_enc = (const float*)d_in[4];
    const float* b_hh_enc = (const float*)d_in[5];
    const float* W_ih_dec = (const float*)d_in[6];
    const float* W_hh_dec = (const float*)d_in[7];
    const float* b_ih_dec = (const float*)d_in[8];
    const float* b_hh_dec = (const float*)d_in[9];
    const float* W_dense  = (const float*)d_in[10];
    const float* b_dense  = (const float*)d_in[11];
    float* out = (float*)d_out;

    cudaFuncSetAttribute(mma_step<0, 8>, cudaFuncAttributeMaxDynamicSharedMemorySize, SMEM_DYN);
    cudaFuncSetAttribute(mma_step<1, 16>, cudaFuncAttributeMaxDynamicSharedMemorySize, SMEM_DYN);

    prep_Bq_kernel<<<384, 256>>>(W_hh_enc, W_hh_dec);
    prep_bc_kernel<<<2, 256>>>(b_ih_enc, b_hh_enc, b_ih_dec, b_hh_dec);
    zero_h_kernel<<<256, 256>>>(0);

    const dim3 grid(16, 8);
    int p = 0;
    for (int t = 0; t < TENC; t++) {
        mma_step<0, 8><<<grid, NT, SMEM_DYN>>>(p, p ^ 1, lag + (size_t)t * BB * 8, W_ih_enc);
        p ^= 1;
    }
    // 168 even -> h_T in g_h[0]
    base_kernel<<<grid, 256>>>(W_ih_dec, b_ih_dec);
    zero_h_kernel<<<256, 256>>>(1);
    int q = 1;
    for (int t = 0; t < TDEC; t++) {
        mma_step<1, 16><<<grid, NT, SMEM_DYN>>>(q, q ^ 1, curr + (size_t)t * BB * 16, W_ih_dec);
        q ^= 1;
        pred_kernel<<<128, 256>>>(q, W_dense, b_dense, out, t);
    }
}